// round 1
// baseline (speedup 1.0000x reference)
#include <cuda_runtime.h>
#include <math.h>

#define MD 1024      // model size D
#define NH 16        // heads
#define HD 64        // head dim
#define NB 8         // batch
#define NS 1024      // seq len
#define MROWS (NB*NS)   // 8192

// ---------------- scratch (static device globals; no allocation allowed) ---
__device__ float g_q[MROWS * MD];          // 32 MB
__device__ float g_kv[MROWS * 2 * MD];     // 64 MB
__device__ float g_heads[MROWS * MD];      // 32 MB

// ---------------------------------------------------------------------------
// Tiled fp32 GEMM with bias:  C[M,N] = A[M,K] @ W[K,N] + bias[N]
// BM=128, BN=128, BK=16, 8x8 microtile, 256 threads. All dims divide tiles.
// ---------------------------------------------------------------------------
template<int BM, int BN, int BK>
__global__ __launch_bounds__(256)
void sgemm_bias(const float* __restrict__ A, const float* __restrict__ W,
                const float* __restrict__ bias, float* __restrict__ C,
                int M, int N, int K)
{
    constexpr int TM = 8, TN = 8;
    __shared__ float As[BK][BM];   // transposed A tile
    __shared__ float Bs[BK][BN];

    const int tid = threadIdx.x;
    const int tx  = tid % (BN / TN);   // 0..15
    const int ty  = tid / (BN / TN);   // 0..15
    const int bn  = blockIdx.x;
    const int bm  = blockIdx.y;

    const float* Ab = A + (size_t)bm * BM * K;
    const float* Wb = W + (size_t)bn * BN;

    float acc[TM][TN];
#pragma unroll
    for (int i = 0; i < TM; i++)
#pragma unroll
        for (int j = 0; j < TN; j++) acc[i][j] = 0.0f;

    // load index mapping (float4 granularity)
    const int arow = tid / (BK / 4);           // 0..63 for BK=16
    const int acol = (tid % (BK / 4)) * 4;
    const int brow = tid / (BN / 4);           // 0..7 for BN=128
    const int bcol = (tid % (BN / 4)) * 4;
    constexpr int AR_STEP = 256 / (BK / 4);    // 64
    constexpr int BR_STEP = 256 / (BN / 4);    // 8

    for (int k0 = 0; k0 < K; k0 += BK) {
#pragma unroll
        for (int r = 0; r < BM; r += AR_STEP) {
            float4 a = *(const float4*)(Ab + (size_t)(arow + r) * K + k0 + acol);
            As[acol + 0][arow + r] = a.x;
            As[acol + 1][arow + r] = a.y;
            As[acol + 2][arow + r] = a.z;
            As[acol + 3][arow + r] = a.w;
        }
#pragma unroll
        for (int r = 0; r < BK; r += BR_STEP) {
            *(float4*)&Bs[brow + r][bcol] =
                *(const float4*)(Wb + (size_t)(k0 + brow + r) * N + bcol);
        }
        __syncthreads();

#pragma unroll
        for (int kk = 0; kk < BK; kk++) {
            float ra[TM], rb[TN];
            *(float4*)&ra[0] = *(float4*)&As[kk][ty * TM];
            *(float4*)&ra[4] = *(float4*)&As[kk][ty * TM + 4];
            *(float4*)&rb[0] = *(float4*)&Bs[kk][tx * TN];
            *(float4*)&rb[4] = *(float4*)&Bs[kk][tx * TN + 4];
#pragma unroll
            for (int i = 0; i < TM; i++)
#pragma unroll
                for (int j = 0; j < TN; j++)
                    acc[i][j] = fmaf(ra[i], rb[j], acc[i][j]);
        }
        __syncthreads();
    }

#pragma unroll
    for (int i = 0; i < TM; i++) {
        float* Crow = C + (size_t)(bm * BM + ty * TM + i) * N + (size_t)bn * BN;
#pragma unroll
        for (int j = 0; j < TN; j += 4) {
            const int col = tx * TN + j;
            float4 o;
            o.x = acc[i][j + 0] + bias[bn * BN + col + 0];
            o.y = acc[i][j + 1] + bias[bn * BN + col + 1];
            o.z = acc[i][j + 2] + bias[bn * BN + col + 2];
            o.w = acc[i][j + 3] + bias[bn * BN + col + 3];
            *(float4*)(Crow + col) = o;
        }
    }
}

// ---------------------------------------------------------------------------
// Flash-attention style fused softmax attention.
// Grid: (S/64, H, B). Block: 256 threads (16x16).
// Each CTA: 64 q-rows of one head. Loops over 16 k-tiles of 64 rows.
// Online softmax stats replicated in registers across the 16-lane row group.
// Dynamic smem: Qs[64][64] (d-major) + Ks[64][64] (d-major) + Vs[64][64]
//               + Ps[64][68]  = 66560 bytes.
// ---------------------------------------------------------------------------
#define ATTN_SMEM ((3 * 64 * 64 + 64 * 68) * 4)

__global__ __launch_bounds__(256)
void attn_kernel(const float* __restrict__ q, const float* __restrict__ kv,
                 float* __restrict__ heads)
{
    extern __shared__ float sm[];
    float* Qs = sm;               // [d][q]  (64x64)
    float* Ks = Qs + 64 * 64;     // [d][k]  (64x64)
    float* Vs = Ks + 64 * 64;     // [k][d]  (64x64)
    float* Ps = Vs + 64 * 64;     // [q][68] padded

    const int b  = blockIdx.z;
    const int h  = blockIdx.y;
    const int qt = blockIdx.x;
    const int tid = threadIdx.x;
    const int tx = tid & 15;      // k / d micro-col group
    const int ty = tid >> 4;      // q micro-row group
    const float scale = 0.125f;   // 1/sqrt(64)

    // ---- load Q tile (scaled), store transposed [d][q] ----
#pragma unroll
    for (int it = 0; it < 4; it++) {
        const int idx = tid + it * 256;            // 1024 float4 slots
        const int row = idx >> 4;                  // q-local 0..63
        const int dc  = (idx & 15) << 2;           // d 0..60
        const float4 v = *(const float4*)(q +
            ((size_t)(b * NS + qt * 64 + row) * MD + h * HD + dc));
        Qs[(dc + 0) * 64 + row] = v.x * scale;
        Qs[(dc + 1) * 64 + row] = v.y * scale;
        Qs[(dc + 2) * 64 + row] = v.z * scale;
        Qs[(dc + 3) * 64 + row] = v.w * scale;
    }

    float m_run[4], l_run[4], O[4][4];
#pragma unroll
    for (int i = 0; i < 4; i++) {
        m_run[i] = -INFINITY;
        l_run[i] = 0.0f;
#pragma unroll
        for (int j = 0; j < 4; j++) O[i][j] = 0.0f;
    }

    for (int kt = 0; kt < NS / 64; kt++) {
        __syncthreads();   // prev iter's P·V done (also covers Q-load visibility)

        // ---- load K tile ([d][k] transposed) and V tile ([k][d]) ----
#pragma unroll
        for (int it = 0; it < 4; it++) {
            const int idx = tid + it * 256;
            const int row = idx >> 4;              // k-local 0..63
            const int dc  = (idx & 15) << 2;
            const size_t base = (size_t)(b * NS + kt * 64 + row) * (2 * MD);
            const float4 kk = *(const float4*)(kv + base + h * HD + dc);
            Ks[(dc + 0) * 64 + row] = kk.x;
            Ks[(dc + 1) * 64 + row] = kk.y;
            Ks[(dc + 2) * 64 + row] = kk.z;
            Ks[(dc + 3) * 64 + row] = kk.w;
            const float4 vv = *(const float4*)(kv + base + MD + h * HD + dc);
            *(float4*)&Vs[row * 64 + dc] = vv;
        }
        __syncthreads();

        // ---- S = Q K^T  (4x4 microtile per thread) ----
        float acc[4][4];
#pragma unroll
        for (int i = 0; i < 4; i++)
#pragma unroll
            for (int j = 0; j < 4; j++) acc[i][j] = 0.0f;

#pragma unroll 8
        for (int d = 0; d < 64; d++) {
            const float4 qv = *(const float4*)&Qs[d * 64 + ty * 4];
            const float4 kq = *(const float4*)&Ks[d * 64 + tx * 4];
            acc[0][0] = fmaf(qv.x, kq.x, acc[0][0]);
            acc[0][1] = fmaf(qv.x, kq.y, acc[0][1]);
            acc[0][2] = fmaf(qv.x, kq.z, acc[0][2]);
            acc[0][3] = fmaf(qv.x, kq.w, acc[0][3]);
            acc[1][0] = fmaf(qv.y, kq.x, acc[1][0]);
            acc[1][1] = fmaf(qv.y, kq.y, acc[1][1]);
            acc[1][2] = fmaf(qv.y, kq.z, acc[1][2]);
            acc[1][3] = fmaf(qv.y, kq.w, acc[1][3]);
            acc[2][0] = fmaf(qv.z, kq.x, acc[2][0]);
            acc[2][1] = fmaf(qv.z, kq.y, acc[2][1]);
            acc[2][2] = fmaf(qv.z, kq.z, acc[2][2]);
            acc[2][3] = fmaf(qv.z, kq.w, acc[2][3]);
            acc[3][0] = fmaf(qv.w, kq.x, acc[3][0]);
            acc[3][1] = fmaf(qv.w, kq.y, acc[3][1]);
            acc[3][2] = fmaf(qv.w, kq.z, acc[3][2]);
            acc[3][3] = fmaf(qv.w, kq.w, acc[3][3]);
        }

        // ---- online softmax (row groups = 16 lanes sharing the same ty) ----
#pragma unroll
        for (int i = 0; i < 4; i++) {
            float lm = fmaxf(fmaxf(acc[i][0], acc[i][1]),
                             fmaxf(acc[i][2], acc[i][3]));
#pragma unroll
            for (int off = 8; off >= 1; off >>= 1)
                lm = fmaxf(lm, __shfl_xor_sync(0xffffffffu, lm, off));

            const float m_new = fmaxf(m_run[i], lm);
            const float alpha = __expf(m_run[i] - m_new);   // 0 on first tile
            float ssum = 0.0f;
#pragma unroll
            for (int j = 0; j < 4; j++) {
                acc[i][j] = __expf(acc[i][j] - m_new);
                ssum += acc[i][j];
            }
#pragma unroll
            for (int off = 8; off >= 1; off >>= 1)
                ssum += __shfl_xor_sync(0xffffffffu, ssum, off);

            l_run[i] = l_run[i] * alpha + ssum;
            m_run[i] = m_new;
#pragma unroll
            for (int j = 0; j < 4; j++) O[i][j] *= alpha;

            *(float4*)&Ps[(ty * 4 + i) * 68 + tx * 4] =
                make_float4(acc[i][0], acc[i][1], acc[i][2], acc[i][3]);
        }
        __syncthreads();

        // ---- O += P @ V ----
#pragma unroll 8
        for (int k = 0; k < 64; k++) {
            const float4 vv = *(const float4*)&Vs[k * 64 + tx * 4];
#pragma unroll
            for (int i = 0; i < 4; i++) {
                const float p = Ps[(ty * 4 + i) * 68 + k];
                O[i][0] = fmaf(p, vv.x, O[i][0]);
                O[i][1] = fmaf(p, vv.y, O[i][1]);
                O[i][2] = fmaf(p, vv.z, O[i][2]);
                O[i][3] = fmaf(p, vv.w, O[i][3]);
            }
        }
    }

    // ---- normalize & write heads[b, q, h*64 + d] ----
#pragma unroll
    for (int i = 0; i < 4; i++) {
        const float inv = 1.0f / l_run[i];
        float4 o = make_float4(O[i][0] * inv, O[i][1] * inv,
                               O[i][2] * inv, O[i][3] * inv);
        *(float4*)(heads + ((size_t)(b * NS + qt * 64 + ty * 4 + i) * MD
                            + h * HD + tx * 4)) = o;
    }
}

// ---------------------------------------------------------------------------
extern "C" void kernel_launch(void* const* d_in, const int* in_sizes, int n_in,
                              void* d_out, int out_size)
{
    (void)in_sizes; (void)n_in; (void)out_size;
    const float* query = (const float*)d_in[0];
    const float* value = (const float*)d_in[1];
    const float* Wq    = (const float*)d_in[2];
    const float* bq    = (const float*)d_in[3];
    const float* Wkv   = (const float*)d_in[4];
    const float* bkv   = (const float*)d_in[5];
    const float* Wo    = (const float*)d_in[6];
    const float* bo    = (const float*)d_in[7];
    float* out = (float*)d_out;

    float *q_buf, *kv_buf, *heads_buf;
    cudaGetSymbolAddress((void**)&q_buf, g_q);
    cudaGetSymbolAddress((void**)&kv_buf, g_kv);
    cudaGetSymbolAddress((void**)&heads_buf, g_heads);

    cudaFuncSetAttribute(attn_kernel,
                         cudaFuncAttributeMaxDynamicSharedMemorySize, ATTN_SMEM);

    const dim3 blk(256);

    // q = query @ Wq + bq           [8192,1024] x [1024,1024]
    sgemm_bias<128,128,16><<<dim3(MD/128, MROWS/128), blk>>>(
        query, Wq, bq, q_buf, MROWS, MD, MD);

    // kv = value @ Wkv + bkv        [8192,1024] x [1024,2048]
    sgemm_bias<128,128,16><<<dim3(2*MD/128, MROWS/128), blk>>>(
        value, Wkv, bkv, kv_buf, MROWS, 2*MD, MD);

    // fused attention               -> heads [8192,1024]
    attn_kernel<<<dim3(NS/64, NH, NB), blk, ATTN_SMEM>>>(q_buf, kv_buf, heads_buf);

    // out = heads @ Wo + bo         [8192,1024] x [1024,1024]
    sgemm_bias<128,128,16><<<dim3(MD/128, MROWS/128), blk>>>(
        heads_buf, Wo, bo, out, MROWS, MD, MD);
}

// round 3
// speedup vs baseline: 1.1851x; 1.1851x over previous
#include <cuda_runtime.h>
#include <math.h>
#include <stdint.h>
#include <mma.h>

using namespace nvcuda;

#define MD 1024      // model size D
#define NH 16        // heads
#define HD 64        // head dim
#define NB 8         // batch
#define NS 1024      // seq len
#define MROWS (NB*NS)   // 8192

// ---------------- scratch (static device globals; no allocation allowed) ---
__device__ float g_q[MROWS * MD];          // 32 MB
__device__ float g_kv[MROWS * 2 * MD];     // 64 MB
__device__ float g_heads[MROWS * MD];      // 32 MB

// ======================== cp.async helpers (Ampere+, non-'a') ==============
static __device__ __forceinline__ void cp_async16(void* dst_smem, const void* src_gmem) {
    unsigned s = (unsigned)__cvta_generic_to_shared(dst_smem);
    asm volatile("cp.async.cg.shared.global [%0], [%1], 16;" :: "r"(s), "l"(src_gmem));
}
#define CP_COMMIT()  asm volatile("cp.async.commit_group;" ::: "memory")
#define CP_WAIT(n)   asm volatile("cp.async.wait_group %0;" :: "n"(n) : "memory")

// ---------------------------------------------------------------------------
// wmma tf32 GEMM:  C[M,N] = A[M,K] @ W[K,N]   (bias added by epilogue kernel)
// BM=128, BN=128, BK=32; 256 threads = 8 warps (4 x 2), warp tile 32x64.
// Double-buffered smem with cp.async. K, M, N multiples of tile dims.
// ---------------------------------------------------------------------------
#define BM 128
#define BN 128
#define BKK 32
#define ASTR (BKK + 4)     // 36 floats
#define BSTR (BN + 4)      // 132 floats
#define GEMM_SMEM ((2 * BM * ASTR + 2 * BKK * BSTR) * 4)   // 70656 bytes

__global__ __launch_bounds__(256)
void gemm_wmma(const float* __restrict__ A, const float* __restrict__ W,
               float* __restrict__ C, int M, int N, int K)
{
    extern __shared__ float sm[];
    float (*As)[BM][ASTR] = (float (*)[BM][ASTR])sm;
    float (*Bs)[BKK][BSTR] = (float (*)[BKK][BSTR])(sm + 2 * BM * ASTR);

    const int tid = threadIdx.x;
    const int wid = tid >> 5;
    const int warpM = wid >> 1;     // 0..3  -> 32-row strip
    const int warpN = wid & 1;      // 0..1  -> 64-col strip
    const int bm = blockIdx.y, bn = blockIdx.x;

    const float* Ab = A + (size_t)bm * BM * K;
    const float* Wb = W + (size_t)bn * BN;

    wmma::fragment<wmma::accumulator, 16, 16, 8, float> cf[2][4];
#pragma unroll
    for (int i = 0; i < 2; i++)
#pragma unroll
        for (int j = 0; j < 4; j++)
            wmma::fill_fragment(cf[i][j], 0.0f);

    // per-thread load slots (4 x 16B for A, 4 x 16B for B per tile)
    const int ar = tid >> 1;                 // with i*256 offset: rows 0..127
    const int NT = K / BKK;

#define LOAD_TILE(t, buf)                                                      \
    do {                                                                       \
        const int k0 = (t) * BKK;                                              \
        _Pragma("unroll")                                                      \
        for (int i = 0; i < 4; i++) {                                          \
            const int idx = tid + i * 256;                                     \
            const int r_a = idx >> 3, c_a = (idx & 7) * 4;                     \
            cp_async16(&As[buf][r_a][c_a], Ab + (size_t)r_a * K + k0 + c_a);   \
            const int r_b = idx >> 5, c_b = (idx & 31) * 4;                    \
            cp_async16(&Bs[buf][r_b][c_b], Wb + (size_t)(k0 + r_b) * N + c_b); \
        }                                                                      \
    } while (0)

    LOAD_TILE(0, 0);
    CP_COMMIT();

    for (int t = 0; t < NT; t++) {
        const int buf = t & 1;
        if (t + 1 < NT) {
            LOAD_TILE(t + 1, buf ^ 1);
            CP_COMMIT();
            CP_WAIT(1);
        } else {
            CP_WAIT(0);
        }
        __syncthreads();

#pragma unroll
        for (int ks = 0; ks < BKK; ks += 8) {
            wmma::fragment<wmma::matrix_a, 16, 16, 8, wmma::precision::tf32,
                           wmma::row_major> af[2];
            wmma::fragment<wmma::matrix_b, 16, 16, 8, wmma::precision::tf32,
                           wmma::row_major> bf[4];
#pragma unroll
            for (int i = 0; i < 2; i++) {
                wmma::load_matrix_sync(af[i], &As[buf][warpM * 32 + i * 16][ks], ASTR);
#pragma unroll
                for (int e = 0; e < af[i].num_elements; e++)
                    af[i].x[e] = wmma::__float_to_tf32(af[i].x[e]);
            }
#pragma unroll
            for (int j = 0; j < 4; j++) {
                wmma::load_matrix_sync(bf[j], &Bs[buf][ks][warpN * 64 + j * 16], BSTR);
#pragma unroll
                for (int e = 0; e < bf[j].num_elements; e++)
                    bf[j].x[e] = wmma::__float_to_tf32(bf[j].x[e]);
            }
#pragma unroll
            for (int i = 0; i < 2; i++)
#pragma unroll
                for (int j = 0; j < 4; j++)
                    wmma::mma_sync(cf[i][j], af[i], bf[j], cf[i][j]);
        }
        __syncthreads();
    }

    // ---- store accumulators straight to global ----
#pragma unroll
    for (int i = 0; i < 2; i++) {
#pragma unroll
        for (int j = 0; j < 4; j++) {
            float* Cp = C + (size_t)(bm * BM + warpM * 32 + i * 16) * N
                          + (size_t)bn * BN + warpN * 64 + j * 16;
            wmma::store_matrix_sync(Cp, cf[i][j], N, wmma::mem_row_major);
        }
    }
#undef LOAD_TILE
}

// ---------------------------------------------------------------------------
// bias epilogue: C[m][n] += bias[n]   (float4 grid-stride)
// ---------------------------------------------------------------------------
__global__ void bias_add(float* __restrict__ C, const float* __restrict__ bias,
                         int N, long long total4)
{
    const long long stride = (long long)gridDim.x * blockDim.x;
    for (long long i = (long long)blockIdx.x * blockDim.x + threadIdx.x;
         i < total4; i += stride) {
        const long long e = i * 4;
        const int n = (int)(e % N);
        float4 c = *(float4*)(C + e);
        const float4 b = *(const float4*)(bias + n);
        c.x += b.x; c.y += b.y; c.z += b.z; c.w += b.w;
        *(float4*)(C + e) = c;
    }
}

// ---------------------------------------------------------------------------
// Flash-attention style fused softmax attention (validated in round 1).
// ---------------------------------------------------------------------------
#define ATTN_SMEM ((3 * 64 * 64 + 64 * 68) * 4)

__global__ __launch_bounds__(256)
void attn_kernel(const float* __restrict__ q, const float* __restrict__ kv,
                 float* __restrict__ heads)
{
    extern __shared__ float smf[];
    float* Qs = smf;              // [d][q]  (64x64)
    float* Ks = Qs + 64 * 64;     // [d][k]  (64x64)
    float* Vs = Ks + 64 * 64;     // [k][d]  (64x64)
    float* Ps = Vs + 64 * 64;     // [q][68] padded

    const int b  = blockIdx.z;
    const int h  = blockIdx.y;
    const int qt = blockIdx.x;
    const int tid = threadIdx.x;
    const int tx = tid & 15;
    const int ty = tid >> 4;
    const float scale = 0.125f;

#pragma unroll
    for (int it = 0; it < 4; it++) {
        const int idx = tid + it * 256;
        const int row = idx >> 4;
        const int dc  = (idx & 15) << 2;
        const float4 v = *(const float4*)(q +
            ((size_t)(b * NS + qt * 64 + row) * MD + h * HD + dc));
        Qs[(dc + 0) * 64 + row] = v.x * scale;
        Qs[(dc + 1) * 64 + row] = v.y * scale;
        Qs[(dc + 2) * 64 + row] = v.z * scale;
        Qs[(dc + 3) * 64 + row] = v.w * scale;
    }

    float m_run[4], l_run[4], O[4][4];
#pragma unroll
    for (int i = 0; i < 4; i++) {
        m_run[i] = -INFINITY;
        l_run[i] = 0.0f;
#pragma unroll
        for (int j = 0; j < 4; j++) O[i][j] = 0.0f;
    }

    for (int kt = 0; kt < NS / 64; kt++) {
        __syncthreads();

#pragma unroll
        for (int it = 0; it < 4; it++) {
            const int idx = tid + it * 256;
            const int row = idx >> 4;
            const int dc  = (idx & 15) << 2;
            const size_t base = (size_t)(b * NS + kt * 64 + row) * (2 * MD);
            const float4 kk = *(const float4*)(kv + base + h * HD + dc);
            Ks[(dc + 0) * 64 + row] = kk.x;
            Ks[(dc + 1) * 64 + row] = kk.y;
            Ks[(dc + 2) * 64 + row] = kk.z;
            Ks[(dc + 3) * 64 + row] = kk.w;
            const float4 vv = *(const float4*)(kv + base + MD + h * HD + dc);
            *(float4*)&Vs[row * 64 + dc] = vv;
        }
        __syncthreads();

        float acc[4][4];
#pragma unroll
        for (int i = 0; i < 4; i++)
#pragma unroll
            for (int j = 0; j < 4; j++) acc[i][j] = 0.0f;

#pragma unroll 8
        for (int d = 0; d < 64; d++) {
            const float4 qv = *(const float4*)&Qs[d * 64 + ty * 4];
            const float4 kq = *(const float4*)&Ks[d * 64 + tx * 4];
            acc[0][0] = fmaf(qv.x, kq.x, acc[0][0]);
            acc[0][1] = fmaf(qv.x, kq.y, acc[0][1]);
            acc[0][2] = fmaf(qv.x, kq.z, acc[0][2]);
            acc[0][3] = fmaf(qv.x, kq.w, acc[0][3]);
            acc[1][0] = fmaf(qv.y, kq.x, acc[1][0]);
            acc[1][1] = fmaf(qv.y, kq.y, acc[1][1]);
            acc[1][2] = fmaf(qv.y, kq.z, acc[1][2]);
            acc[1][3] = fmaf(qv.y, kq.w, acc[1][3]);
            acc[2][0] = fmaf(qv.z, kq.x, acc[2][0]);
            acc[2][1] = fmaf(qv.z, kq.y, acc[2][1]);
            acc[2][2] = fmaf(qv.z, kq.z, acc[2][2]);
            acc[2][3] = fmaf(qv.z, kq.w, acc[2][3]);
            acc[3][0] = fmaf(qv.w, kq.x, acc[3][0]);
            acc[3][1] = fmaf(qv.w, kq.y, acc[3][1]);
            acc[3][2] = fmaf(qv.w, kq.z, acc[3][2]);
            acc[3][3] = fmaf(qv.w, kq.w, acc[3][3]);
        }

#pragma unroll
        for (int i = 0; i < 4; i++) {
            float lm = fmaxf(fmaxf(acc[i][0], acc[i][1]),
                             fmaxf(acc[i][2], acc[i][3]));
#pragma unroll
            for (int off = 8; off >= 1; off >>= 1)
                lm = fmaxf(lm, __shfl_xor_sync(0xffffffffu, lm, off));

            const float m_new = fmaxf(m_run[i], lm);
            const float alpha = __expf(m_run[i] - m_new);
            float ssum = 0.0f;
#pragma unroll
            for (int j = 0; j < 4; j++) {
                acc[i][j] = __expf(acc[i][j] - m_new);
                ssum += acc[i][j];
            }
#pragma unroll
            for (int off = 8; off >= 1; off >>= 1)
                ssum += __shfl_xor_sync(0xffffffffu, ssum, off);

            l_run[i] = l_run[i] * alpha + ssum;
            m_run[i] = m_new;
#pragma unroll
            for (int j = 0; j < 4; j++) O[i][j] *= alpha;

            *(float4*)&Ps[(ty * 4 + i) * 68 + tx * 4] =
                make_float4(acc[i][0], acc[i][1], acc[i][2], acc[i][3]);
        }
        __syncthreads();

#pragma unroll 8
        for (int k = 0; k < 64; k++) {
            const float4 vv = *(const float4*)&Vs[k * 64 + tx * 4];
#pragma unroll
            for (int i = 0; i < 4; i++) {
                const float p = Ps[(ty * 4 + i) * 68 + k];
                O[i][0] = fmaf(p, vv.x, O[i][0]);
                O[i][1] = fmaf(p, vv.y, O[i][1]);
                O[i][2] = fmaf(p, vv.z, O[i][2]);
                O[i][3] = fmaf(p, vv.w, O[i][3]);
            }
        }
    }

#pragma unroll
    for (int i = 0; i < 4; i++) {
        const float inv = 1.0f / l_run[i];
        float4 o = make_float4(O[i][0] * inv, O[i][1] * inv,
                               O[i][2] * inv, O[i][3] * inv);
        *(float4*)(heads + ((size_t)(b * NS + qt * 64 + ty * 4 + i) * MD
                            + h * HD + tx * 4)) = o;
    }
}

// ---------------------------------------------------------------------------
extern "C" void kernel_launch(void* const* d_in, const int* in_sizes, int n_in,
                              void* d_out, int out_size)
{
    (void)in_sizes; (void)n_in; (void)out_size;
    const float* query = (const float*)d_in[0];
    const float* value = (const float*)d_in[1];
    const float* Wq    = (const float*)d_in[2];
    const float* bq    = (const float*)d_in[3];
    const float* Wkv   = (const float*)d_in[4];
    const float* bkv   = (const float*)d_in[5];
    const float* Wo    = (const float*)d_in[6];
    const float* bo    = (const float*)d_in[7];
    float* out = (float*)d_out;

    float *q_buf, *kv_buf, *heads_buf;
    cudaGetSymbolAddress((void**)&q_buf, g_q);
    cudaGetSymbolAddress((void**)&kv_buf, g_kv);
    cudaGetSymbolAddress((void**)&heads_buf, g_heads);

    cudaFuncSetAttribute(attn_kernel,
                         cudaFuncAttributeMaxDynamicSharedMemorySize, ATTN_SMEM);
    cudaFuncSetAttribute(gemm_wmma,
                         cudaFuncAttributeMaxDynamicSharedMemorySize, GEMM_SMEM);

    // ---- q = query @ Wq + bq ----
    gemm_wmma<<<dim3(MD / BN, MROWS / BM), 256, GEMM_SMEM>>>(
        query, Wq, q_buf, MROWS, MD, MD);
    bias_add<<<2048, 256>>>(q_buf, bq, MD, (long long)MROWS * MD / 4);

    // ---- kv = value @ Wkv + bkv ----
    gemm_wmma<<<dim3(2 * MD / BN, MROWS / BM), 256, GEMM_SMEM>>>(
        value, Wkv, kv_buf, MROWS, 2 * MD, MD);
    bias_add<<<2048, 256>>>(kv_buf, bkv, 2 * MD, (long long)MROWS * 2 * MD / 4);

    // ---- fused attention ----
    attn_kernel<<<dim3(NS / 64, NH, NB), 256, ATTN_SMEM>>>(q_buf, kv_buf, heads_buf);

    // ---- out = heads @ Wo + bo ----
    gemm_wmma<<<dim3(MD / BN, MROWS / BM), 256, GEMM_SMEM>>>(
        heads_buf, Wo, out, MROWS, MD, MD);
    bias_add<<<2048, 256>>>(out, bo, MD, (long long)MROWS * MD / 4);
}

// round 4
// speedup vs baseline: 1.7975x; 1.5167x over previous
#include <cuda_runtime.h>
#include <math.h>
#include <stdint.h>

#define MD 1024      // model size D
#define NH 16        // heads
#define HD 64        // head dim
#define NB 8         // batch
#define NS 1024      // seq len
#define MROWS (NB*NS)   // 8192

// ---------------- scratch (static device globals; no allocation allowed) ---
__device__ float g_q[MROWS * MD];          // 32 MB
__device__ float g_kv[MROWS * 2 * MD];     // 64 MB
__device__ float g_heads[MROWS * MD];      // 32 MB
__device__ float g_wt[2 * MD * MD];        // 8 MB transposed (tf32-rounded) W

// ======================== PTX helpers ======================================
static __device__ __forceinline__ void cp_async16(void* dst_smem, const void* src_gmem) {
    unsigned s = (unsigned)__cvta_generic_to_shared(dst_smem);
    asm volatile("cp.async.cg.shared.global [%0], [%1], 16;" :: "r"(s), "l"(src_gmem));
}
#define CP_COMMIT()  asm volatile("cp.async.commit_group;" ::: "memory")
#define CP_WAIT(n)   asm volatile("cp.async.wait_group %0;" :: "n"(n) : "memory")

static __device__ __forceinline__ uint32_t cvt_tf32(uint32_t x) {
    uint32_t r;
    asm("cvt.rna.tf32.f32 %0, %1;" : "=r"(r) : "f"(__uint_as_float(x)));
    return r;
}
static __device__ __forceinline__ float tf32_round_f(float x) {
    uint32_t r;
    asm("cvt.rna.tf32.f32 %0, %1;" : "=r"(r) : "f"(x));
    return __uint_as_float(r);
}
static __device__ __forceinline__ void ldsm4(uint32_t* r, uint32_t addr) {
    asm volatile("ldmatrix.sync.aligned.m8n8.x4.shared.b16 {%0,%1,%2,%3}, [%4];"
        : "=r"(r[0]), "=r"(r[1]), "=r"(r[2]), "=r"(r[3]) : "r"(addr));
}
static __device__ __forceinline__ void mma8(float* c, const uint32_t* a,
                                            uint32_t b0, uint32_t b1) {
    asm volatile("mma.sync.aligned.m16n8k8.row.col.f32.tf32.tf32.f32 "
        "{%0,%1,%2,%3}, {%4,%5,%6,%7}, {%8,%9}, {%0,%1,%2,%3};"
        : "+f"(c[0]), "+f"(c[1]), "+f"(c[2]), "+f"(c[3])
        : "r"(a[0]), "r"(a[1]), "r"(a[2]), "r"(a[3]), "r"(b0), "r"(b1));
}
// 128-byte-row XOR swizzle: byte bits [4:6] ^= bits [7:9]
#define SWZ(o) ((o) ^ ((((uint32_t)(o)) >> 3) & 0x70u))

// ---------------------------------------------------------------------------
// Weight transpose + tf32 pre-round: Wt[n][k] = tf32(W[k][n]).
// Block (32,8), grid (N/32, K/32).
// ---------------------------------------------------------------------------
__global__ void transpose_k(const float* __restrict__ W, float* __restrict__ Wt,
                            int K, int N)
{
    __shared__ float t[32][33];
    const int n0 = blockIdx.x * 32, k0 = blockIdx.y * 32;
    const int tx = threadIdx.x, ty = threadIdx.y;
#pragma unroll
    for (int j = 0; j < 32; j += 8)
        t[ty + j][tx] = W[(size_t)(k0 + ty + j) * N + n0 + tx];
    __syncthreads();
#pragma unroll
    for (int j = 0; j < 32; j += 8)
        Wt[(size_t)(n0 + ty + j) * K + k0 + tx] = tf32_round_f(t[tx][ty + j]);
}

// ---------------------------------------------------------------------------
// tf32 mma GEMM (ldmatrix b16-view):  C[M,N] = A[M,K] @ Bt[N,K]^T + bias[N]
// CTA 128x128, BK=32, 8 warps (2 x 4) of 64x32, cp.async double buffer.
// smem: 2 stages x (A 16KB + B 16KB) = 64KB.
// ---------------------------------------------------------------------------
#define GEMM_SMEM 65536

__global__ __launch_bounds__(256)
void gemm_tc(const float* __restrict__ A, const float* __restrict__ Bt,
             const float* __restrict__ bias, float* __restrict__ C,
             int M, int N, int K)
{
    extern __shared__ char smem[];
    const int tid  = threadIdx.x;
    const int lane = tid & 31;
    const int wid  = tid >> 5;
    const int warpM = wid >> 2;    // 0..1  -> 64-row strip
    const int warpN = wid & 3;     // 0..3  -> 32-col strip
    const int bm = blockIdx.y, bn = blockIdx.x;

    const float* Ab = A  + (size_t)bm * 128 * K;
    const float* Bb = Bt + (size_t)bn * 128 * K;

    float c[4][4][4];
#pragma unroll
    for (int i = 0; i < 4; i++)
#pragma unroll
        for (int j = 0; j < 4; j++)
#pragma unroll
            for (int e = 0; e < 4; e++) c[i][j][e] = 0.0f;

    const uint32_t sbase = (uint32_t)__cvta_generic_to_shared(smem);

    // ---- ldmatrix per-thread address precompute ----
    // A x4 tile (m16 x k8): lanes 0-7 rows0-7/k+0 | 8-15 rows8-15/k+0
    //                       | 16-23 rows0-7/k+16B | 24-31 rows8-15/k+16B
    const int l7 = lane & 7;
    const int rA = l7 + ((lane >> 3) & 1) * 8;
    const uint32_t kA = ((lane >> 4) & 1) * 16;
    uint32_t aRow[4], aXor[4];
#pragma unroll
    for (int i = 0; i < 4; i++) {
        const int row = warpM * 64 + i * 16 + rA;
        aRow[i] = (uint32_t)row * 128u;
        aXor[i] = (uint32_t)(row & 7) * 16u;
    }
    // B x4 tile (n16 x k8): lanes 0-7 n0-7/k+0 | 8-15 n0-7/k+16B
    //                       | 16-23 n8-15/k+0 | 24-31 n8-15/k+16B
    const int rB = l7 + ((lane >> 4) & 1) * 8;
    const uint32_t kB = ((lane >> 3) & 1) * 16;
    uint32_t bRow[2], bXor[2];
#pragma unroll
    for (int j = 0; j < 2; j++) {
        const int row = warpN * 32 + j * 16 + rB;
        bRow[j] = (uint32_t)row * 128u;
        bXor[j] = (uint32_t)(row & 7) * 16u;
    }

    const int NT = K / 32;

#define LOAD_TILE(t, buf)                                                      \
    do {                                                                       \
        const int k0 = (t) * 32;                                               \
        char* sA = smem + (buf) * 32768;                                       \
        char* sB = sA + 16384;                                                 \
        _Pragma("unroll")                                                      \
        for (int i = 0; i < 4; i++) {                                          \
            const int idx = tid + i * 256;                                     \
            const int row = idx >> 3, at = idx & 7;                            \
            const uint32_t off = SWZ((uint32_t)(row * 128 + at * 16));         \
            cp_async16(sA + off, Ab + (size_t)row * K + k0 + at * 4);          \
            cp_async16(sB + off, Bb + (size_t)row * K + k0 + at * 4);          \
        }                                                                      \
    } while (0)

    LOAD_TILE(0, 0);
    CP_COMMIT();

    for (int t = 0; t < NT; t++) {
        const int buf = t & 1;
        if (t + 1 < NT) {
            LOAD_TILE(t + 1, buf ^ 1);
            CP_COMMIT();
            CP_WAIT(1);
        } else {
            CP_WAIT(0);
        }
        __syncthreads();

        const uint32_t aBase = sbase + buf * 32768;
        const uint32_t bBase = aBase + 16384;

#pragma unroll
        for (int slab = 0; slab < 4; slab++) {
            uint32_t a[4][4], b[2][4];
            const uint32_t sb = (uint32_t)slab * 32u;
#pragma unroll
            for (int i = 0; i < 4; i++)
                ldsm4(a[i], aBase + aRow[i] + ((sb + kA) ^ aXor[i]));
#pragma unroll
            for (int j = 0; j < 2; j++)
                ldsm4(b[j], bBase + bRow[j] + ((sb + kB) ^ bXor[j]));
            // A is raw fp32: round to tf32; B was pre-rounded in transpose_k.
#pragma unroll
            for (int i = 0; i < 4; i++)
#pragma unroll
                for (int e = 0; e < 4; e++) a[i][e] = cvt_tf32(a[i][e]);
#pragma unroll
            for (int mi = 0; mi < 4; mi++)
#pragma unroll
                for (int nj = 0; nj < 4; nj++)
                    mma8(c[mi][nj], a[mi],
                         b[nj >> 1][(nj & 1) * 2], b[nj >> 1][(nj & 1) * 2 + 1]);
        }
        __syncthreads();
    }
#undef LOAD_TILE

    // ---- epilogue: write accumulators + bias ----
#pragma unroll
    for (int mi = 0; mi < 4; mi++) {
        const int row0 = bm * 128 + warpM * 64 + mi * 16 + (lane >> 2);
#pragma unroll
        for (int nj = 0; nj < 4; nj++) {
            const int col = bn * 128 + warpN * 32 + nj * 8 + (lane & 3) * 2;
            const float2 bv = *(const float2*)(bias + col);
            float2 o0, o1;
            o0.x = c[mi][nj][0] + bv.x;  o0.y = c[mi][nj][1] + bv.y;
            o1.x = c[mi][nj][2] + bv.x;  o1.y = c[mi][nj][3] + bv.y;
            *(float2*)(C + (size_t)row0 * N + col) = o0;
            *(float2*)(C + (size_t)(row0 + 8) * N + col) = o1;
        }
    }
}

// ---------------------------------------------------------------------------
// Flash-attention style fused softmax attention (validated since round 1).
// ---------------------------------------------------------------------------
#define ATTN_SMEM ((3 * 64 * 64 + 64 * 68) * 4)

__global__ __launch_bounds__(256)
void attn_kernel(const float* __restrict__ q, const float* __restrict__ kv,
                 float* __restrict__ heads)
{
    extern __shared__ float smf[];
    float* Qs = smf;              // [d][q]  (64x64)
    float* Ks = Qs + 64 * 64;     // [d][k]  (64x64)
    float* Vs = Ks + 64 * 64;     // [k][d]  (64x64)
    float* Ps = Vs + 64 * 64;     // [q][68] padded

    const int b  = blockIdx.z;
    const int h  = blockIdx.y;
    const int qt = blockIdx.x;
    const int tid = threadIdx.x;
    const int tx = tid & 15;
    const int ty = tid >> 4;
    const float scale = 0.125f;

#pragma unroll
    for (int it = 0; it < 4; it++) {
        const int idx = tid + it * 256;
        const int row = idx >> 4;
        const int dc  = (idx & 15) << 2;
        const float4 v = *(const float4*)(q +
            ((size_t)(b * NS + qt * 64 + row) * MD + h * HD + dc));
        Qs[(dc + 0) * 64 + row] = v.x * scale;
        Qs[(dc + 1) * 64 + row] = v.y * scale;
        Qs[(dc + 2) * 64 + row] = v.z * scale;
        Qs[(dc + 3) * 64 + row] = v.w * scale;
    }

    float m_run[4], l_run[4], O[4][4];
#pragma unroll
    for (int i = 0; i < 4; i++) {
        m_run[i] = -INFINITY;
        l_run[i] = 0.0f;
#pragma unroll
        for (int j = 0; j < 4; j++) O[i][j] = 0.0f;
    }

    for (int kt = 0; kt < NS / 64; kt++) {
        __syncthreads();

#pragma unroll
        for (int it = 0; it < 4; it++) {
            const int idx = tid + it * 256;
            const int row = idx >> 4;
            const int dc  = (idx & 15) << 2;
            const size_t base = (size_t)(b * NS + kt * 64 + row) * (2 * MD);
            const float4 kk = *(const float4*)(kv + base + h * HD + dc);
            Ks[(dc + 0) * 64 + row] = kk.x;
            Ks[(dc + 1) * 64 + row] = kk.y;
            Ks[(dc + 2) * 64 + row] = kk.z;
            Ks[(dc + 3) * 64 + row] = kk.w;
            const float4 vv = *(const float4*)(kv + base + MD + h * HD + dc);
            *(float4*)&Vs[row * 64 + dc] = vv;
        }
        __syncthreads();

        float acc[4][4];
#pragma unroll
        for (int i = 0; i < 4; i++)
#pragma unroll
            for (int j = 0; j < 4; j++) acc[i][j] = 0.0f;

#pragma unroll 8
        for (int d = 0; d < 64; d++) {
            const float4 qv = *(const float4*)&Qs[d * 64 + ty * 4];
            const float4 kq = *(const float4*)&Ks[d * 64 + tx * 4];
            acc[0][0] = fmaf(qv.x, kq.x, acc[0][0]);
            acc[0][1] = fmaf(qv.x, kq.y, acc[0][1]);
            acc[0][2] = fmaf(qv.x, kq.z, acc[0][2]);
            acc[0][3] = fmaf(qv.x, kq.w, acc[0][3]);
            acc[1][0] = fmaf(qv.y, kq.x, acc[1][0]);
            acc[1][1] = fmaf(qv.y, kq.y, acc[1][1]);
            acc[1][2] = fmaf(qv.y, kq.z, acc[1][2]);
            acc[1][3] = fmaf(qv.y, kq.w, acc[1][3]);
            acc[2][0] = fmaf(qv.z, kq.x, acc[2][0]);
            acc[2][1] = fmaf(qv.z, kq.y, acc[2][1]);
            acc[2][2] = fmaf(qv.z, kq.z, acc[2][2]);
            acc[2][3] = fmaf(qv.z, kq.w, acc[2][3]);
            acc[3][0] = fmaf(qv.w, kq.x, acc[3][0]);
            acc[3][1] = fmaf(qv.w, kq.y, acc[3][1]);
            acc[3][2] = fmaf(qv.w, kq.z, acc[3][2]);
            acc[3][3] = fmaf(qv.w, kq.w, acc[3][3]);
        }

#pragma unroll
        for (int i = 0; i < 4; i++) {
            float lm = fmaxf(fmaxf(acc[i][0], acc[i][1]),
                             fmaxf(acc[i][2], acc[i][3]));
#pragma unroll
            for (int off = 8; off >= 1; off >>= 1)
                lm = fmaxf(lm, __shfl_xor_sync(0xffffffffu, lm, off));

            const float m_new = fmaxf(m_run[i], lm);
            const float alpha = __expf(m_run[i] - m_new);
            float ssum = 0.0f;
#pragma unroll
            for (int j = 0; j < 4; j++) {
                acc[i][j] = __expf(acc[i][j] - m_new);
                ssum += acc[i][j];
            }
#pragma unroll
            for (int off = 8; off >= 1; off >>= 1)
                ssum += __shfl_xor_sync(0xffffffffu, ssum, off);

            l_run[i] = l_run[i] * alpha + ssum;
            m_run[i] = m_new;
#pragma unroll
            for (int j = 0; j < 4; j++) O[i][j] *= alpha;

            *(float4*)&Ps[(ty * 4 + i) * 68 + tx * 4] =
                make_float4(acc[i][0], acc[i][1], acc[i][2], acc[i][3]);
        }
        __syncthreads();

#pragma unroll 8
        for (int k = 0; k < 64; k++) {
            const float4 vv = *(const float4*)&Vs[k * 64 + tx * 4];
#pragma unroll
            for (int i = 0; i < 4; i++) {
                const float p = Ps[(ty * 4 + i) * 68 + k];
                O[i][0] = fmaf(p, vv.x, O[i][0]);
                O[i][1] = fmaf(p, vv.y, O[i][1]);
                O[i][2] = fmaf(p, vv.z, O[i][2]);
                O[i][3] = fmaf(p, vv.w, O[i][3]);
            }
        }
    }

#pragma unroll
    for (int i = 0; i < 4; i++) {
        const float inv = 1.0f / l_run[i];
        float4 o = make_float4(O[i][0] * inv, O[i][1] * inv,
                               O[i][2] * inv, O[i][3] * inv);
        *(float4*)(heads + ((size_t)(b * NS + qt * 64 + ty * 4 + i) * MD
                            + h * HD + tx * 4)) = o;
    }
}

// ---------------------------------------------------------------------------
extern "C" void kernel_launch(void* const* d_in, const int* in_sizes, int n_in,
                              void* d_out, int out_size)
{
    (void)in_sizes; (void)n_in; (void)out_size;
    const float* query = (const float*)d_in[0];
    const float* value = (const float*)d_in[1];
    const float* Wq    = (const float*)d_in[2];
    const float* bq    = (const float*)d_in[3];
    const float* Wkv   = (const float*)d_in[4];
    const float* bkv   = (const float*)d_in[5];
    const float* Wo    = (const float*)d_in[6];
    const float* bo    = (const float*)d_in[7];
    float* out = (float*)d_out;

    float *q_buf, *kv_buf, *heads_buf, *wt_buf;
    cudaGetSymbolAddress((void**)&q_buf, g_q);
    cudaGetSymbolAddress((void**)&kv_buf, g_kv);
    cudaGetSymbolAddress((void**)&heads_buf, g_heads);
    cudaGetSymbolAddress((void**)&wt_buf, g_wt);

    cudaFuncSetAttribute(attn_kernel,
                         cudaFuncAttributeMaxDynamicSharedMemorySize, ATTN_SMEM);
    cudaFuncSetAttribute(gemm_tc,
                         cudaFuncAttributeMaxDynamicSharedMemorySize, GEMM_SMEM);

    const dim3 tblk(32, 8);

    // ---- q = query @ Wq + bq ----
    transpose_k<<<dim3(MD / 32, MD / 32), tblk>>>(Wq, wt_buf, MD, MD);
    gemm_tc<<<dim3(MD / 128, MROWS / 128), 256, GEMM_SMEM>>>(
        query, wt_buf, bq, q_buf, MROWS, MD, MD);

    // ---- kv = value @ Wkv + bkv ----
    transpose_k<<<dim3(2 * MD / 32, MD / 32), tblk>>>(Wkv, wt_buf, MD, 2 * MD);
    gemm_tc<<<dim3(2 * MD / 128, MROWS / 128), 256, GEMM_SMEM>>>(
        value, wt_buf, bkv, kv_buf, MROWS, 2 * MD, MD);

    // ---- fused attention ----
    attn_kernel<<<dim3(NS / 64, NH, NB), 256, ATTN_SMEM>>>(q_buf, kv_buf, heads_buf);

    // ---- out = heads @ Wo + bo ----
    transpose_k<<<dim3(MD / 32, MD / 32), tblk>>>(Wo, wt_buf, MD, MD);
    gemm_tc<<<dim3(MD / 128, MROWS / 128), 256, GEMM_SMEM>>>(
        heads_buf, wt_buf, bo, out, MROWS, MD, MD);
}

// round 8
// speedup vs baseline: 3.7856x; 2.1060x over previous
#include <cuda_runtime.h>
#include <math.h>
#include <stdint.h>

#define MD 1024      // model size D
#define NH 16        // heads
#define HD 64        // head dim
#define NB 8         // batch
#define NS 1024      // seq len
#define MROWS (NB*NS)   // 8192

// ---------------- scratch (static device globals; no allocation allowed) ---
__device__ float g_q[MROWS * MD];          // 32 MB
__device__ float g_kv[MROWS * 2 * MD];     // 64 MB
__device__ float g_heads[MROWS * MD];      // 32 MB
__device__ float g_wt[2 * MD * MD];        // 8 MB transposed (tf32-rounded) W

// ======================== PTX helpers ======================================
static __device__ __forceinline__ void cp_async16(void* dst_smem, const void* src_gmem) {
    unsigned s = (unsigned)__cvta_generic_to_shared(dst_smem);
    asm volatile("cp.async.cg.shared.global [%0], [%1], 16;" :: "r"(s), "l"(src_gmem));
}
#define CP_COMMIT()  asm volatile("cp.async.commit_group;" ::: "memory")
#define CP_WAIT(n)   asm volatile("cp.async.wait_group %0;" :: "n"(n) : "memory")

static __device__ __forceinline__ uint32_t cvt_tf32(uint32_t x) {
    uint32_t r;
    asm("cvt.rna.tf32.f32 %0, %1;" : "=r"(r) : "f"(__uint_as_float(x)));
    return r;
}
static __device__ __forceinline__ uint32_t cvt_tf32_f(float x) {
    uint32_t r;
    asm("cvt.rna.tf32.f32 %0, %1;" : "=r"(r) : "f"(x));
    return r;
}
static __device__ __forceinline__ float tf32_round_f(float x) {
    return __uint_as_float(cvt_tf32_f(x));
}
static __device__ __forceinline__ void ldsm4(uint32_t* r, uint32_t addr) {
    asm volatile("ldmatrix.sync.aligned.m8n8.x4.shared.b16 {%0,%1,%2,%3}, [%4];"
        : "=r"(r[0]), "=r"(r[1]), "=r"(r[2]), "=r"(r[3]) : "r"(addr));
}
static __device__ __forceinline__ void mma8(float* c, const uint32_t* a,
                                            uint32_t b0, uint32_t b1) {
    asm volatile("mma.sync.aligned.m16n8k8.row.col.f32.tf32.tf32.f32 "
        "{%0,%1,%2,%3}, {%4,%5,%6,%7}, {%8,%9}, {%0,%1,%2,%3};"
        : "+f"(c[0]), "+f"(c[1]), "+f"(c[2]), "+f"(c[3])
        : "r"(a[0]), "r"(a[1]), "r"(a[2]), "r"(a[3]), "r"(b0), "r"(b1));
}
// 128-byte-row XOR swizzle: byte bits [4:6] ^= bits [7:9]
#define SWZ(o) ((o) ^ ((((uint32_t)(o)) >> 3) & 0x70u))

// ---------------------------------------------------------------------------
// Weight transpose + tf32 pre-round: Wt[n][k] = tf32(W[k][n]).
// ---------------------------------------------------------------------------
__global__ void transpose_k(const float* __restrict__ W, float* __restrict__ Wt,
                            int K, int N)
{
    __shared__ float t[32][33];
    const int n0 = blockIdx.x * 32, k0 = blockIdx.y * 32;
    const int tx = threadIdx.x, ty = threadIdx.y;
#pragma unroll
    for (int j = 0; j < 32; j += 8)
        t[ty + j][tx] = W[(size_t)(k0 + ty + j) * N + n0 + tx];
    __syncthreads();
#pragma unroll
    for (int j = 0; j < 32; j += 8)
        Wt[(size_t)(n0 + ty + j) * K + k0 + tx] = tf32_round_f(t[tx][ty + j]);
}

// ---------------------------------------------------------------------------
// tf32 mma GEMM (unchanged from round 4):  C = A @ Bt^T + bias
// ---------------------------------------------------------------------------
#define GEMM_SMEM 65536

__global__ __launch_bounds__(256)
void gemm_tc(const float* __restrict__ A, const float* __restrict__ Bt,
             const float* __restrict__ bias, float* __restrict__ C,
             int M, int N, int K)
{
    extern __shared__ char smem[];
    const int tid  = threadIdx.x;
    const int lane = tid & 31;
    const int wid  = tid >> 5;
    const int warpM = wid >> 2;
    const int warpN = wid & 3;
    const int bm = blockIdx.y, bn = blockIdx.x;

    const float* Ab = A  + (size_t)bm * 128 * K;
    const float* Bb = Bt + (size_t)bn * 128 * K;

    float c[4][4][4];
#pragma unroll
    for (int i = 0; i < 4; i++)
#pragma unroll
        for (int j = 0; j < 4; j++)
#pragma unroll
            for (int e = 0; e < 4; e++) c[i][j][e] = 0.0f;

    const uint32_t sbase = (uint32_t)__cvta_generic_to_shared(smem);

    const int l7 = lane & 7;
    const int rA = l7 + ((lane >> 3) & 1) * 8;
    const uint32_t kA = ((lane >> 4) & 1) * 16;
    uint32_t aRow[4], aXor[4];
#pragma unroll
    for (int i = 0; i < 4; i++) {
        const int row = warpM * 64 + i * 16 + rA;
        aRow[i] = (uint32_t)row * 128u;
        aXor[i] = (uint32_t)(row & 7) * 16u;
    }
    const int rB = l7 + ((lane >> 4) & 1) * 8;
    const uint32_t kB = ((lane >> 3) & 1) * 16;
    uint32_t bRow[2], bXor[2];
#pragma unroll
    for (int j = 0; j < 2; j++) {
        const int row = warpN * 32 + j * 16 + rB;
        bRow[j] = (uint32_t)row * 128u;
        bXor[j] = (uint32_t)(row & 7) * 16u;
    }

    const int NT = K / 32;

#define LOAD_TILE(t, buf)                                                      \
    do {                                                                       \
        const int k0 = (t) * 32;                                               \
        char* sA = smem + (buf) * 32768;                                       \
        char* sB = sA + 16384;                                                 \
        _Pragma("unroll")                                                      \
        for (int i = 0; i < 4; i++) {                                          \
            const int idx = tid + i * 256;                                     \
            const int row = idx >> 3, at = idx & 7;                            \
            const uint32_t off = SWZ((uint32_t)(row * 128 + at * 16));         \
            cp_async16(sA + off, Ab + (size_t)row * K + k0 + at * 4);          \
            cp_async16(sB + off, Bb + (size_t)row * K + k0 + at * 4);          \
        }                                                                      \
    } while (0)

    LOAD_TILE(0, 0);
    CP_COMMIT();

    for (int t = 0; t < NT; t++) {
        const int buf = t & 1;
        if (t + 1 < NT) {
            LOAD_TILE(t + 1, buf ^ 1);
            CP_COMMIT();
            CP_WAIT(1);
        } else {
            CP_WAIT(0);
        }
        __syncthreads();

        const uint32_t aBase = sbase + buf * 32768;
        const uint32_t bBase = aBase + 16384;

#pragma unroll
        for (int slab = 0; slab < 4; slab++) {
            uint32_t a[4][4], b[2][4];
            const uint32_t sb = (uint32_t)slab * 32u;
#pragma unroll
            for (int i = 0; i < 4; i++)
                ldsm4(a[i], aBase + aRow[i] + ((sb + kA) ^ aXor[i]));
#pragma unroll
            for (int j = 0; j < 2; j++)
                ldsm4(b[j], bBase + bRow[j] + ((sb + kB) ^ bXor[j]));
#pragma unroll
            for (int i = 0; i < 4; i++)
#pragma unroll
                for (int e = 0; e < 4; e++) a[i][e] = cvt_tf32(a[i][e]);
#pragma unroll
            for (int mi = 0; mi < 4; mi++)
#pragma unroll
                for (int nj = 0; nj < 4; nj++)
                    mma8(c[mi][nj], a[mi],
                         b[nj >> 1][(nj & 1) * 2], b[nj >> 1][(nj & 1) * 2 + 1]);
        }
        __syncthreads();
    }
#undef LOAD_TILE

#pragma unroll
    for (int mi = 0; mi < 4; mi++) {
        const int row0 = bm * 128 + warpM * 64 + mi * 16 + (lane >> 2);
#pragma unroll
        for (int nj = 0; nj < 4; nj++) {
            const int col = bn * 128 + warpN * 32 + nj * 8 + (lane & 3) * 2;
            const float2 bv = *(const float2*)(bias + col);
            float2 o0, o1;
            o0.x = c[mi][nj][0] + bv.x;  o0.y = c[mi][nj][1] + bv.y;
            o1.x = c[mi][nj][2] + bv.x;  o1.y = c[mi][nj][3] + bv.y;
            *(float2*)(C + (size_t)row0 * N + col) = o0;
            *(float2*)(C + (size_t)(row0 + 8) * N + col) = o1;
        }
    }
}

// ---------------------------------------------------------------------------
// Tensor-core flash attention (tf32 mma, online softmax in registers).
// Grid (NS/128, NH, NB), 256 threads (8 warps x 16 q-rows).
// smem layout (bytes):
//   Q:     0      2 panels x 16384  ([128 q][32 d] swizzled, x2 d-panels)
//   P:     32768  2 panels x 16384  ([128 q][32 k])
//   K:     65536  2 panels x 8192   ([64 k][32 d])
//   Vt:    81920  2 panels x 8192   ([64 d][32 k])
//   Vtemp: 98304  2 panels x 8192   ([64 k][32 d] raw fp32)
// total 114688 bytes; 2 CTAs/SM.
// ---------------------------------------------------------------------------
#define ATTN_SMEM 114688

__global__ __launch_bounds__(256, 2)
void attn_tc(const float* __restrict__ q, const float* __restrict__ kv,
             float* __restrict__ heads)
{
    extern __shared__ char smc[];
    const uint32_t sb = (uint32_t)__cvta_generic_to_shared(smc);
    const uint32_t Qb = sb, Pb = sb + 32768, Kb = sb + 65536, Vtb = sb + 81920;

    const int b = blockIdx.z, h = blockIdx.y, qt = blockIdx.x;
    const int tid = threadIdx.x, lane = tid & 31, w = tid >> 5;
    const float scale = 0.125f;   // 1/sqrt(64)

    // ---- load Q once (scaled + tf32-rounded) ----
#pragma unroll
    for (int i = 0; i < 8; i++) {
        const int idx = tid + i * 256;
        const int row = idx >> 4, f4 = idx & 15;
        const float4 v = *(const float4*)(q +
            ((size_t)(b * NS + qt * 128 + row) * MD + h * HD + f4 * 4));
        uint4 u;
        u.x = cvt_tf32_f(v.x * scale); u.y = cvt_tf32_f(v.y * scale);
        u.z = cvt_tf32_f(v.z * scale); u.w = cvt_tf32_f(v.w * scale);
        *(uint4*)(smc + (f4 >> 3) * 16384 + SWZ((uint32_t)(row * 128 + (f4 & 7) * 16))) = u;
    }

    // ---- ldmatrix address precompute ----
    const int l7 = lane & 7;
    const int rA = l7 + ((lane >> 3) & 1) * 8;
    const uint32_t kA = ((lane >> 4) & 1) * 16;
    const int aRowLocal = w * 16 + rA;
    const uint32_t aRowOff = (uint32_t)aRowLocal * 128u;
    const uint32_t aXor = (uint32_t)(aRowLocal & 7) * 16u;

    const int rB = l7 + ((lane >> 4) & 1) * 8;
    const uint32_t kB = ((lane >> 3) & 1) * 16;
    uint32_t bRowOff[4], bXor[4];
#pragma unroll
    for (int j = 0; j < 4; j++) {
        const int rowb = j * 16 + rB;
        bRowOff[j] = (uint32_t)rowb * 128u;
        bXor[j] = (uint32_t)(rowb & 7) * 16u;
    }

    float O[8][4];
#pragma unroll
    for (int nj = 0; nj < 8; nj++)
#pragma unroll
        for (int e = 0; e < 4; e++) O[nj][e] = 0.0f;
    float m_run[2] = { -INFINITY, -INFINITY };
    float l_run[2] = { 0.0f, 0.0f };

    for (int kt = 0; kt < NS / 64; kt++) {
        __syncthreads();   // prev PV done with K/Vt/P; Q visible (first iter)

        // ---- load K (tf32) and V (raw) tiles ----
#pragma unroll
        for (int i = 0; i < 4; i++) {
            const int idx = tid + i * 256;
            const int krow = idx >> 4, f4 = idx & 15;
            const size_t gbase = (size_t)(b * NS + kt * 64 + krow) * (2 * MD)
                               + h * HD + f4 * 4;
            const uint32_t off = (f4 >> 3) * 8192 + SWZ((uint32_t)(krow * 128 + (f4 & 7) * 16));
            const float4 kk = *(const float4*)(kv + gbase);
            uint4 uk;
            uk.x = cvt_tf32_f(kk.x); uk.y = cvt_tf32_f(kk.y);
            uk.z = cvt_tf32_f(kk.z); uk.w = cvt_tf32_f(kk.w);
            *(uint4*)(smc + 65536 + off) = uk;
            const float4 vv = *(const float4*)(kv + gbase + MD);
            *(float4*)(smc + 98304 + off) = vv;
        }
        __syncthreads();

        // ---- S = Q K^T (warp: 16 q-rows x 64 keys) ----
        float sacc[8][4];
#pragma unroll
        for (int nj = 0; nj < 8; nj++)
#pragma unroll
            for (int e = 0; e < 4; e++) sacc[nj][e] = 0.0f;

#pragma unroll
        for (int slab = 0; slab < 8; slab++) {
            const uint32_t so = (uint32_t)(slab & 3) * 32u;
            uint32_t a[4], bb[4][4];
            ldsm4(a, Qb + (slab >> 2) * 16384 + aRowOff + ((so + kA) ^ aXor));
#pragma unroll
            for (int j = 0; j < 4; j++)
                ldsm4(bb[j], Kb + (slab >> 2) * 8192 + bRowOff[j] + ((so + kB) ^ bXor[j]));
#pragma unroll
            for (int nj = 0; nj < 8; nj++)
                mma8(sacc[nj], a, bb[nj >> 1][(nj & 1) * 2], bb[nj >> 1][(nj & 1) * 2 + 1]);
        }

        // ---- transpose V: Vtemp[k][d] -> Vt[d][k] (tf32) ----
        {
            const int d = tid & 63, kg = tid >> 6;
            const uint32_t rdbase = 98304 + (d >> 5) * 8192;
            const uint32_t wcol = (uint32_t)(d & 31) * 4u;
#pragma unroll
            for (int t = 0; t < 16; t++) {
                const int k = kg * 16 + t;
                const uint32_t rv = *(const uint32_t*)(smc + rdbase +
                    SWZ((uint32_t)(k * 128) + wcol));
                *(uint32_t*)(smc + 81920 + (k >> 5) * 8192 +
                    SWZ((uint32_t)(d * 128 + (k & 31) * 4))) = cvt_tf32(rv);
            }
        }

        // ---- online softmax + P store ----
#pragma unroll
        for (int r = 0; r < 2; r++) {
            float mx = -INFINITY;
#pragma unroll
            for (int nj = 0; nj < 8; nj++)
                mx = fmaxf(mx, fmaxf(sacc[nj][2 * r], sacc[nj][2 * r + 1]));
            mx = fmaxf(mx, __shfl_xor_sync(0xffffffffu, mx, 1));
            mx = fmaxf(mx, __shfl_xor_sync(0xffffffffu, mx, 2));

            const float m_new = fmaxf(m_run[r], mx);
            const float al = __expf(m_run[r] - m_new);
            float sum = 0.0f;
#pragma unroll
            for (int nj = 0; nj < 8; nj++) {
                const float p0 = __expf(sacc[nj][2 * r] - m_new);
                const float p1 = __expf(sacc[nj][2 * r + 1] - m_new);
                sacc[nj][2 * r] = p0; sacc[nj][2 * r + 1] = p1;
                sum += p0 + p1;
            }
            sum += __shfl_xor_sync(0xffffffffu, sum, 1);
            sum += __shfl_xor_sync(0xffffffffu, sum, 2);

            l_run[r] = l_run[r] * al + sum;
            m_run[r] = m_new;
#pragma unroll
            for (int nj = 0; nj < 8; nj++) {
                O[nj][2 * r] *= al;
                O[nj][2 * r + 1] *= al;
            }
            const int prow = w * 16 + (lane >> 2) + r * 8;
#pragma unroll
            for (int nj = 0; nj < 8; nj++) {
                uint2 pv;
                pv.x = cvt_tf32_f(sacc[nj][2 * r]);
                pv.y = cvt_tf32_f(sacc[nj][2 * r + 1]);
                *(uint2*)(smc + 32768 + (nj >> 2) * 16384 +
                    SWZ((uint32_t)(prow * 128 + (nj & 3) * 32 + (lane & 3) * 8))) = pv;
            }
        }
        __syncthreads();   // Vt + P complete across CTA

        // ---- O += P V ----
#pragma unroll
        for (int slab = 0; slab < 8; slab++) {
            const uint32_t so = (uint32_t)(slab & 3) * 32u;
            uint32_t a[4], bb[4][4];
            ldsm4(a, Pb + (slab >> 2) * 16384 + aRowOff + ((so + kA) ^ aXor));
#pragma unroll
            for (int j = 0; j < 4; j++)
                ldsm4(bb[j], Vtb + (slab >> 2) * 8192 + bRowOff[j] + ((so + kB) ^ bXor[j]));
#pragma unroll
            for (int nj = 0; nj < 8; nj++)
                mma8(O[nj], a, bb[nj >> 1][(nj & 1) * 2], bb[nj >> 1][(nj & 1) * 2 + 1]);
        }
    }

    // ---- normalize and write heads ----
#pragma unroll
    for (int r = 0; r < 2; r++) {
        const float inv = 1.0f / l_run[r];
        const size_t row = (size_t)(b * NS + qt * 128 + w * 16 + (lane >> 2) + r * 8);
#pragma unroll
        for (int nj = 0; nj < 8; nj++) {
            const int col = h * HD + nj * 8 + (lane & 3) * 2;
            float2 o;
            o.x = O[nj][2 * r] * inv;
            o.y = O[nj][2 * r + 1] * inv;
            *(float2*)(heads + row * MD + col) = o;
        }
    }
}

// ---------------------------------------------------------------------------
extern "C" void kernel_launch(void* const* d_in, const int* in_sizes, int n_in,
                              void* d_out, int out_size)
{
    (void)in_sizes; (void)n_in; (void)out_size;
    const float* query = (const float*)d_in[0];
    const float* value = (const float*)d_in[1];
    const float* Wq    = (const float*)d_in[2];
    const float* bq    = (const float*)d_in[3];
    const float* Wkv   = (const float*)d_in[4];
    const float* bkv   = (const float*)d_in[5];
    const float* Wo    = (const float*)d_in[6];
    const float* bo    = (const float*)d_in[7];
    float* out = (float*)d_out;

    float *q_buf, *kv_buf, *heads_buf, *wt_buf;
    cudaGetSymbolAddress((void**)&q_buf, g_q);
    cudaGetSymbolAddress((void**)&kv_buf, g_kv);
    cudaGetSymbolAddress((void**)&heads_buf, g_heads);
    cudaGetSymbolAddress((void**)&wt_buf, g_wt);

    cudaFuncSetAttribute(attn_tc,
                         cudaFuncAttributeMaxDynamicSharedMemorySize, ATTN_SMEM);
    cudaFuncSetAttribute(gemm_tc,
                         cudaFuncAttributeMaxDynamicSharedMemorySize, GEMM_SMEM);

    const dim3 tblk(32, 8);

    // ---- q = query @ Wq + bq ----
    transpose_k<<<dim3(MD / 32, MD / 32), tblk>>>(Wq, wt_buf, MD, MD);
    gemm_tc<<<dim3(MD / 128, MROWS / 128), 256, GEMM_SMEM>>>(
        query, wt_buf, bq, q_buf, MROWS, MD, MD);

    // ---- kv = value @ Wkv + bkv ----
    transpose_k<<<dim3(2 * MD / 32, MD / 32), tblk>>>(Wkv, wt_buf, MD, 2 * MD);
    gemm_tc<<<dim3(2 * MD / 128, MROWS / 128), 256, GEMM_SMEM>>>(
        value, wt_buf, bkv, kv_buf, MROWS, 2 * MD, MD);

    // ---- fused tensor-core attention ----
    attn_tc<<<dim3(NS / 128, NH, NB), 256, ATTN_SMEM>>>(q_buf, kv_buf, heads_buf);

    // ---- out = heads @ Wo + bo ----
    transpose_k<<<dim3(MD / 32, MD / 32), tblk>>>(Wo, wt_buf, MD, MD);
    gemm_tc<<<dim3(MD / 128, MROWS / 128), 256, GEMM_SMEM>>>(
        heads_buf, wt_buf, bo, out, MROWS, MD, MD);
}

// round 11
// speedup vs baseline: 5.1889x; 1.3707x over previous
#include <cuda_runtime.h>
#include <cuda_fp16.h>
#include <math.h>
#include <stdint.h>

#define MD 1024      // model size D
#define NH 16        // heads
#define HD 64        // head dim
#define NB 8         // batch
#define NS 1024      // seq len
#define MROWS (NB*NS)   // 8192

// ---------------- scratch (static device globals; no allocation allowed) ---
__device__ __half g_xh[MROWS * MD];        // 16 MB (converted query OR value)
__device__ __half g_q16[MROWS * MD];       // 16 MB
__device__ __half g_kv16[MROWS * 2 * MD];  // 32 MB
__device__ __half g_h16[MROWS * MD];       // 16 MB
__device__ __half g_wt16[2 * MD * MD];     // 4 MB transposed fp16 weights

// ======================== PTX helpers ======================================
static __device__ __forceinline__ void cp_async16(void* dst_smem, const void* src_gmem) {
    unsigned s = (unsigned)__cvta_generic_to_shared(dst_smem);
    asm volatile("cp.async.cg.shared.global [%0], [%1], 16;" :: "r"(s), "l"(src_gmem));
}
#define CP_COMMIT()  asm volatile("cp.async.commit_group;" ::: "memory")
#define CP_WAIT(n)   asm volatile("cp.async.wait_group %0;" :: "n"(n) : "memory")

static __device__ __forceinline__ void ldsm4(uint32_t* r, uint32_t addr) {
    asm volatile("ldmatrix.sync.aligned.m8n8.x4.shared.b16 {%0,%1,%2,%3}, [%4];"
        : "=r"(r[0]), "=r"(r[1]), "=r"(r[2]), "=r"(r[3]) : "r"(addr));
}
static __device__ __forceinline__ void ldsm4t(uint32_t* r, uint32_t addr) {
    asm volatile("ldmatrix.sync.aligned.m8n8.x4.trans.shared.b16 {%0,%1,%2,%3}, [%4];"
        : "=r"(r[0]), "=r"(r[1]), "=r"(r[2]), "=r"(r[3]) : "r"(addr));
}
static __device__ __forceinline__ void mma16(float* c, const uint32_t* a,
                                             uint32_t b0, uint32_t b1) {
    asm volatile("mma.sync.aligned.m16n8k16.row.col.f32.f16.f16.f32 "
        "{%0,%1,%2,%3}, {%4,%5,%6,%7}, {%8,%9}, {%0,%1,%2,%3};"
        : "+f"(c[0]), "+f"(c[1]), "+f"(c[2]), "+f"(c[3])
        : "r"(a[0]), "r"(a[1]), "r"(a[2]), "r"(a[3]), "r"(b0), "r"(b1));
}
// 128-byte-row XOR swizzle: byte bits [4:6] ^= bits [7:9]
#define SWZ(o) ((o) ^ ((((uint32_t)(o)) >> 3) & 0x70u))

// ---------------------------------------------------------------------------
// fp32 -> fp16 convert (float4 granularity, grid-stride)
// ---------------------------------------------------------------------------
__global__ void f2h(const float* __restrict__ x, __half* __restrict__ y, int n4)
{
    int i = blockIdx.x * blockDim.x + threadIdx.x;
    const int stride = gridDim.x * blockDim.x;
    for (; i < n4; i += stride) {
        const float4 v = ((const float4*)x)[i];
        __half2 h0 = __floats2half2_rn(v.x, v.y);
        __half2 h1 = __floats2half2_rn(v.z, v.w);
        uint2 u;
        u.x = *(uint32_t*)&h0;
        u.y = *(uint32_t*)&h1;
        ((uint2*)y)[i] = u;
    }
}

// ---------------------------------------------------------------------------
// Weight transpose + fp16 round: Wt[n][k] = fp16(W[k][n]).
// ---------------------------------------------------------------------------
__global__ void transpose_h(const float* __restrict__ W, __half* __restrict__ Wt,
                            int K, int N)
{
    __shared__ float t[32][33];
    const int n0 = blockIdx.x * 32, k0 = blockIdx.y * 32;
    const int tx = threadIdx.x, ty = threadIdx.y;
#pragma unroll
    for (int j = 0; j < 32; j += 8)
        t[ty + j][tx] = W[(size_t)(k0 + ty + j) * N + n0 + tx];
    __syncthreads();
#pragma unroll
    for (int j = 0; j < 32; j += 8)
        Wt[(size_t)(n0 + ty + j) * K + k0 + tx] = __float2half_rn(t[tx][ty + j]);
}

// ---------------------------------------------------------------------------
// fp16 mma GEMM:  C[M,N] = A[M,K] @ Bt[N,K]^T + bias[N]
// CTA 128x128, BK=64 (128B fp16 rows), 8 warps (2x4) of 64x32 tiles,
// cp.async double buffer. smem: 2 stages x (A 16KB + B 16KB) = 64KB.
// ---------------------------------------------------------------------------
#define GEMM_SMEM 65536

template<bool HALF_OUT>
__global__ __launch_bounds__(256)
void gemm_h(const __half* __restrict__ A, const __half* __restrict__ Bt,
            const float* __restrict__ bias, void* __restrict__ Cv,
            int M, int N, int K)
{
    extern __shared__ char smem[];
    const int tid  = threadIdx.x;
    const int lane = tid & 31;
    const int wid  = tid >> 5;
    const int warpM = wid >> 2;
    const int warpN = wid & 3;
    const int bm = blockIdx.y, bn = blockIdx.x;

    const __half* Ab = A  + (size_t)bm * 128 * K;
    const __half* Bb = Bt + (size_t)bn * 128 * K;

    float c[4][4][4];
#pragma unroll
    for (int i = 0; i < 4; i++)
#pragma unroll
        for (int j = 0; j < 4; j++)
#pragma unroll
            for (int e = 0; e < 4; e++) c[i][j][e] = 0.0f;

    const uint32_t sbase = (uint32_t)__cvta_generic_to_shared(smem);

    const int l7 = lane & 7;
    const uint32_t xorv = (uint32_t)l7 * 16u;
    const int rA = l7 + ((lane >> 3) & 1) * 8;
    const uint32_t kA = ((lane >> 4) & 1) * 16;
    uint32_t aRow[4];
#pragma unroll
    for (int i = 0; i < 4; i++)
        aRow[i] = (uint32_t)(warpM * 64 + i * 16 + rA) * 128u;
    const int rB = l7 + ((lane >> 4) & 1) * 8;
    const uint32_t kB = ((lane >> 3) & 1) * 16;
    uint32_t bRow[2];
#pragma unroll
    for (int j = 0; j < 2; j++)
        bRow[j] = (uint32_t)(warpN * 32 + j * 16 + rB) * 128u;

    const int NT = K / 64;

#define LOAD_TILE(t, buf)                                                      \
    do {                                                                       \
        const int k0 = (t) * 64;                                               \
        char* sA = smem + (buf) * 32768;                                       \
        char* sB = sA + 16384;                                                 \
        _Pragma("unroll")                                                      \
        for (int i = 0; i < 4; i++) {                                          \
            const int idx = tid + i * 256;                                     \
            const int row = idx >> 3, ch = idx & 7;                            \
            const uint32_t off = SWZ((uint32_t)(row * 128 + ch * 16));         \
            cp_async16(sA + off, Ab + (size_t)row * K + k0 + ch * 8);          \
            cp_async16(sB + off, Bb + (size_t)row * K + k0 + ch * 8);          \
        }                                                                      \
    } while (0)

    LOAD_TILE(0, 0);
    CP_COMMIT();

    for (int t = 0; t < NT; t++) {
        const int buf = t & 1;
        if (t + 1 < NT) {
            LOAD_TILE(t + 1, buf ^ 1);
            CP_COMMIT();
            CP_WAIT(1);
        } else {
            CP_WAIT(0);
        }
        __syncthreads();

        const uint32_t aBase = sbase + buf * 32768;
        const uint32_t bBase = aBase + 16384;

#pragma unroll
        for (int slab = 0; slab < 4; slab++) {
            const uint32_t so = (uint32_t)slab * 32u;
            uint32_t a[4][4], b[2][4];
#pragma unroll
            for (int i = 0; i < 4; i++)
                ldsm4(a[i], aBase + aRow[i] + ((so + kA) ^ xorv));
#pragma unroll
            for (int j = 0; j < 2; j++)
                ldsm4(b[j], bBase + bRow[j] + ((so + kB) ^ xorv));
#pragma unroll
            for (int mi = 0; mi < 4; mi++)
#pragma unroll
                for (int nj = 0; nj < 4; nj++)
                    mma16(c[mi][nj], a[mi],
                          b[nj >> 1][(nj & 1) * 2], b[nj >> 1][(nj & 1) * 2 + 1]);
        }
        __syncthreads();
    }
#undef LOAD_TILE

    // ---- epilogue: accumulators + bias ----
#pragma unroll
    for (int mi = 0; mi < 4; mi++) {
        const int row0 = bm * 128 + warpM * 64 + mi * 16 + (lane >> 2);
#pragma unroll
        for (int nj = 0; nj < 4; nj++) {
            const int col = bn * 128 + warpN * 32 + nj * 8 + (lane & 3) * 2;
            const float2 bv = *(const float2*)(bias + col);
            const float o00 = c[mi][nj][0] + bv.x, o01 = c[mi][nj][1] + bv.y;
            const float o10 = c[mi][nj][2] + bv.x, o11 = c[mi][nj][3] + bv.y;
            if (HALF_OUT) {
                __half* C = (__half*)Cv;
                __half2 h0 = __floats2half2_rn(o00, o01);
                __half2 h1 = __floats2half2_rn(o10, o11);
                *(__half2*)(C + (size_t)row0 * N + col) = h0;
                *(__half2*)(C + (size_t)(row0 + 8) * N + col) = h1;
            } else {
                float* C = (float*)Cv;
                *(float2*)(C + (size_t)row0 * N + col) = make_float2(o00, o01);
                *(float2*)(C + (size_t)(row0 + 8) * N + col) = make_float2(o10, o11);
            }
        }
    }
}

// ---------------------------------------------------------------------------
// fp16 tensor-core flash attention.
// Grid (NS/128, NH, NB), 256 threads (8 warps x 16 q-rows).
// smem (bytes): Q [128][64]h @0 (16KB), P [128][64]h @16384 (16KB),
//               K 2 x [64][64]h @32768 (8KB each), V 2 x [64][64]h @49152.
// Total 64KB. V consumed via ldmatrix.trans (no smem transpose pass).
// ---------------------------------------------------------------------------
#define ATTN_SMEM 65536
#define QOFF 0
#define POFF 16384
#define KOFF 32768
#define VOFF 49152

__global__ __launch_bounds__(256, 2)
void attn_h(const __half* __restrict__ q, const __half* __restrict__ kv,
            __half* __restrict__ heads)
{
    extern __shared__ char smc[];
    const uint32_t sb = (uint32_t)__cvta_generic_to_shared(smc);

    const int b = blockIdx.z, h = blockIdx.y, qt = blockIdx.x;
    const int tid = threadIdx.x, lane = tid & 31, w = tid >> 5;
    const float scale = 0.125f;   // 1/sqrt(64)

    // ---- ldmatrix address precompute ----
    const int l7 = lane & 7;
    const uint32_t xorv = (uint32_t)l7 * 16u;
    const int rA = l7 + ((lane >> 3) & 1) * 8;
    const uint32_t kA = ((lane >> 4) & 1) * 16;
    const uint32_t aRowOff = (uint32_t)(w * 16 + rA) * 128u;

    const int rB = l7 + ((lane >> 4) & 1) * 8;
    const uint32_t kB = ((lane >> 3) & 1) * 16;
    uint32_t bRow[4];
#pragma unroll
    for (int j = 0; j < 4; j++)
        bRow[j] = (uint32_t)(j * 16 + rB) * 128u;

    // V trans-ldmatrix: lane -> source k row and d 16B-half
    const uint32_t vkOff = (uint32_t)(l7 + ((lane >> 3) & 1) * 8) * 128u;
    const uint32_t vdh = ((lane >> 4) & 1) * 16;

    // ---- load Q tile (fp16 direct copies) ----
#pragma unroll
    for (int i = 0; i < 4; i++) {
        const int idx = tid + i * 256;
        const int row = idx >> 3, ch = idx & 7;
        cp_async16(smc + QOFF + SWZ((uint32_t)(row * 128 + ch * 16)),
                   q + (size_t)(b * NS + qt * 128 + row) * MD + h * HD + ch * 8);
    }

    // K/V tile loader (double buffered)
#define ATTN_LOAD(kt, buf)                                                     \
    do {                                                                       \
        _Pragma("unroll")                                                      \
        for (int i = 0; i < 2; i++) {                                          \
            const int idx = tid + i * 256;                                     \
            const int row = idx >> 3, ch = idx & 7;                            \
            const __half* src = kv + (size_t)(b * NS + (kt) * 64 + row) * (2 * MD) \
                              + h * HD + ch * 8;                               \
            const uint32_t off = SWZ((uint32_t)(row * 128 + ch * 16));         \
            cp_async16(smc + KOFF + (buf) * 8192 + off, src);                  \
            cp_async16(smc + VOFF + (buf) * 8192 + off, src + MD);             \
        }                                                                      \
    } while (0)

    ATTN_LOAD(0, 0);
    CP_COMMIT();

    float O[8][4];
#pragma unroll
    for (int nj = 0; nj < 8; nj++)
#pragma unroll
        for (int e = 0; e < 4; e++) O[nj][e] = 0.0f;
    float m_run[2] = { -INFINITY, -INFINITY };
    float l_run[2] = { 0.0f, 0.0f };

    for (int kt = 0; kt < NS / 64; kt++) {
        const int buf = kt & 1;
        if (kt + 1 < NS / 64) {
            ATTN_LOAD(kt + 1, buf ^ 1);
            CP_COMMIT();
            CP_WAIT(1);
        } else {
            CP_WAIT(0);
        }
        __syncthreads();

        const uint32_t Kb = sb + KOFF + buf * 8192;
        const uint32_t Vb = sb + VOFF + buf * 8192;

        // ---- S = Q K^T  (warp: 16 q-rows x 64 keys, k-dim = 64 head dims) ----
        float sacc[8][4];
#pragma unroll
        for (int nj = 0; nj < 8; nj++)
#pragma unroll
            for (int e = 0; e < 4; e++) sacc[nj][e] = 0.0f;

#pragma unroll
        for (int s = 0; s < 4; s++) {
            const uint32_t so = (uint32_t)s * 32u;
            uint32_t a[4], kb[4][4];
            ldsm4(a, sb + QOFF + aRowOff + ((so + kA) ^ xorv));
#pragma unroll
            for (int j = 0; j < 4; j++)
                ldsm4(kb[j], Kb + bRow[j] + ((so + kB) ^ xorv));
#pragma unroll
            for (int j = 0; j < 4; j++) {
                mma16(sacc[2 * j],     a, kb[j][0], kb[j][1]);
                mma16(sacc[2 * j + 1], a, kb[j][2], kb[j][3]);
            }
        }

        // ---- scale + online softmax + P store (fp16) ----
#pragma unroll
        for (int nj = 0; nj < 8; nj++)
#pragma unroll
            for (int e = 0; e < 4; e++) sacc[nj][e] *= scale;

#pragma unroll
        for (int r = 0; r < 2; r++) {
            float mx = -INFINITY;
#pragma unroll
            for (int nj = 0; nj < 8; nj++)
                mx = fmaxf(mx, fmaxf(sacc[nj][2 * r], sacc[nj][2 * r + 1]));
            mx = fmaxf(mx, __shfl_xor_sync(0xffffffffu, mx, 1));
            mx = fmaxf(mx, __shfl_xor_sync(0xffffffffu, mx, 2));

            const float m_new = fmaxf(m_run[r], mx);
            const float al = __expf(m_run[r] - m_new);
            float sum = 0.0f;
#pragma unroll
            for (int nj = 0; nj < 8; nj++) {
                const float p0 = __expf(sacc[nj][2 * r] - m_new);
                const float p1 = __expf(sacc[nj][2 * r + 1] - m_new);
                sacc[nj][2 * r] = p0; sacc[nj][2 * r + 1] = p1;
                sum += p0 + p1;
            }
            sum += __shfl_xor_sync(0xffffffffu, sum, 1);
            sum += __shfl_xor_sync(0xffffffffu, sum, 2);

            l_run[r] = l_run[r] * al + sum;
            m_run[r] = m_new;
#pragma unroll
            for (int nj = 0; nj < 8; nj++) {
                O[nj][2 * r] *= al;
                O[nj][2 * r + 1] *= al;
            }
            const int prow = w * 16 + (lane >> 2) + r * 8;
#pragma unroll
            for (int nj = 0; nj < 8; nj++) {
                __half2 pv = __floats2half2_rn(sacc[nj][2 * r], sacc[nj][2 * r + 1]);
                *(uint32_t*)(smc + POFF +
                    SWZ((uint32_t)(prow * 128 + nj * 16 + (lane & 3) * 4))) =
                    *(uint32_t*)&pv;
            }
        }
        __syncwarp();   // P rows are warp-private; order stores before ldmatrix

        // ---- O += P V   (V via ldmatrix.trans: B[d][k] from V[k][d]) ----
#pragma unroll
        for (int s = 0; s < 4; s++) {
            const uint32_t so = (uint32_t)s * 32u;
            uint32_t a[4];
            ldsm4(a, sb + POFF + aRowOff + ((so + kA) ^ xorv));
#pragma unroll
            for (int jb = 0; jb < 4; jb++) {
                uint32_t bb[4];
                ldsm4t(bb, Vb + s * 2048 + vkOff + ((jb * 32 + vdh) ^ xorv));
                mma16(O[2 * jb],     a, bb[0], bb[1]);
                mma16(O[2 * jb + 1], a, bb[2], bb[3]);
            }
        }
        __syncthreads();   // all warps done with K/V[buf] before next overwrite
    }
#undef ATTN_LOAD

    // ---- normalize and write heads (fp16) ----
#pragma unroll
    for (int r = 0; r < 2; r++) {
        const float inv = 1.0f / l_run[r];
        const size_t row = (size_t)(b * NS + qt * 128 + w * 16 + (lane >> 2) + r * 8);
#pragma unroll
        for (int nj = 0; nj < 8; nj++) {
            const int col = h * HD + nj * 8 + (lane & 3) * 2;
            __half2 o = __floats2half2_rn(O[nj][2 * r] * inv, O[nj][2 * r + 1] * inv);
            *(__half2*)(heads + row * MD + col) = o;
        }
    }
}

// ---------------------------------------------------------------------------
extern "C" void kernel_launch(void* const* d_in, const int* in_sizes, int n_in,
                              void* d_out, int out_size)
{
    (void)in_sizes; (void)n_in; (void)out_size;
    const float* query = (const float*)d_in[0];
    const float* value = (const float*)d_in[1];
    const float* Wq    = (const float*)d_in[2];
    const float* bq    = (const float*)d_in[3];
    const float* Wkv   = (const float*)d_in[4];
    const float* bkv   = (const float*)d_in[5];
    const float* Wo    = (const float*)d_in[6];
    const float* bo    = (const float*)d_in[7];
    float* out = (float*)d_out;

    __half *xh, *q16, *kv16, *h16, *wt16;
    cudaGetSymbolAddress((void**)&xh,   g_xh);
    cudaGetSymbolAddress((void**)&q16,  g_q16);
    cudaGetSymbolAddress((void**)&kv16, g_kv16);
    cudaGetSymbolAddress((void**)&h16,  g_h16);
    cudaGetSymbolAddress((void**)&wt16, g_wt16);

    cudaFuncSetAttribute(attn_h,
                         cudaFuncAttributeMaxDynamicSharedMemorySize, ATTN_SMEM);
    cudaFuncSetAttribute(gemm_h<true>,
                         cudaFuncAttributeMaxDynamicSharedMemorySize, GEMM_SMEM);
    cudaFuncSetAttribute(gemm_h<false>,
                         cudaFuncAttributeMaxDynamicSharedMemorySize, GEMM_SMEM);

    const dim3 tblk(32, 8);
    const int n4 = MROWS * MD / 4;

    // ---- q = query @ Wq + bq ----
    f2h<<<2048, 256>>>(query, xh, n4);
    transpose_h<<<dim3(MD / 32, MD / 32), tblk>>>(Wq, wt16, MD, MD);
    gemm_h<true><<<dim3(MD / 128, MROWS / 128), 256, GEMM_SMEM>>>(
        xh, wt16, bq, q16, MROWS, MD, MD);

    // ---- kv = value @ Wkv + bkv ----
    f2h<<<2048, 256>>>(value, xh, n4);
    transpose_h<<<dim3(2 * MD / 32, MD / 32), tblk>>>(Wkv, wt16, MD, 2 * MD);
    gemm_h<true><<<dim3(2 * MD / 128, MROWS / 128), 256, GEMM_SMEM>>>(
        xh, wt16, bkv, kv16, MROWS, 2 * MD, MD);

    // ---- fused fp16 tensor-core attention ----
    attn_h<<<dim3(NS / 128, NH, NB), 256, ATTN_SMEM>>>(q16, kv16, h16);

    // ---- out = heads @ Wo + bo ----
    transpose_h<<<dim3(MD / 32, MD / 32), tblk>>>(Wo, wt16, MD, MD);
    gemm_h<false><<<dim3(MD / 128, MROWS / 128), 256, GEMM_SMEM>>>(
        h16, wt16, bo, out, MROWS, MD, MD);
}

// round 13
// speedup vs baseline: 7.7748x; 1.4984x over previous
#include <cuda_runtime.h>
#include <cuda_fp16.h>
#include <math.h>
#include <stdint.h>

#define MD 1024      // model size D
#define NH 16        // heads
#define HD 64        // head dim
#define NB 8         // batch
#define NS 1024      // seq len
#define MROWS (NB*NS)   // 8192

// ---------------- scratch (static device globals; no allocation allowed) ---
__device__ __half g_xh[MROWS * MD];        // 16 MB (converted query OR value)
__device__ __half g_q16[MROWS * MD];       // 16 MB
__device__ __half g_kv16[MROWS * 2 * MD];  // 32 MB
__device__ __half g_h16[MROWS * MD];       // 16 MB
__device__ __half g_wt16[2 * MD * MD];     // 4 MB transposed fp16 weights

// ======================== PTX helpers ======================================
static __device__ __forceinline__ void cp_async16(void* dst_smem, const void* src_gmem) {
    unsigned s = (unsigned)__cvta_generic_to_shared(dst_smem);
    asm volatile("cp.async.cg.shared.global [%0], [%1], 16;" :: "r"(s), "l"(src_gmem));
}
#define CP_COMMIT()  asm volatile("cp.async.commit_group;" ::: "memory")
#define CP_WAIT(n)   asm volatile("cp.async.wait_group %0;" :: "n"(n) : "memory")

static __device__ __forceinline__ void ldsm4(uint32_t* r, uint32_t addr) {
    asm volatile("ldmatrix.sync.aligned.m8n8.x4.shared.b16 {%0,%1,%2,%3}, [%4];"
        : "=r"(r[0]), "=r"(r[1]), "=r"(r[2]), "=r"(r[3]) : "r"(addr));
}
static __device__ __forceinline__ void ldsm4t(uint32_t* r, uint32_t addr) {
    asm volatile("ldmatrix.sync.aligned.m8n8.x4.trans.shared.b16 {%0,%1,%2,%3}, [%4];"
        : "=r"(r[0]), "=r"(r[1]), "=r"(r[2]), "=r"(r[3]) : "r"(addr));
}
static __device__ __forceinline__ void mma16(float* c, const uint32_t* a,
                                             uint32_t b0, uint32_t b1) {
    asm volatile("mma.sync.aligned.m16n8k16.row.col.f32.f16.f16.f32 "
        "{%0,%1,%2,%3}, {%4,%5,%6,%7}, {%8,%9}, {%0,%1,%2,%3};"
        : "+f"(c[0]), "+f"(c[1]), "+f"(c[2]), "+f"(c[3])
        : "r"(a[0]), "r"(a[1]), "r"(a[2]), "r"(a[3]), "r"(b0), "r"(b1));
}
// 128-byte-row XOR swizzle: byte bits [4:6] ^= bits [7:9]
#define SWZ(o) ((o) ^ ((((uint32_t)(o)) >> 3) & 0x70u))

// ---------------------------------------------------------------------------
// fp32 -> fp16 convert (float4 granularity, grid-stride)
// ---------------------------------------------------------------------------
__global__ void f2h(const float* __restrict__ x, __half* __restrict__ y, int n4)
{
    int i = blockIdx.x * blockDim.x + threadIdx.x;
    const int stride = gridDim.x * blockDim.x;
    for (; i < n4; i += stride) {
        const float4 v = ((const float4*)x)[i];
        __half2 h0 = __floats2half2_rn(v.x, v.y);
        __half2 h1 = __floats2half2_rn(v.z, v.w);
        uint2 u;
        u.x = *(uint32_t*)&h0;
        u.y = *(uint32_t*)&h1;
        ((uint2*)y)[i] = u;
    }
}

// ---------------------------------------------------------------------------
// Weight transpose + fp16 round: Wt[n][k] = fp16(W[k][n]).
// ---------------------------------------------------------------------------
__global__ void transpose_h(const float* __restrict__ W, __half* __restrict__ Wt,
                            int K, int N)
{
    __shared__ float t[32][33];
    const int n0 = blockIdx.x * 32, k0 = blockIdx.y * 32;
    const int tx = threadIdx.x, ty = threadIdx.y;
#pragma unroll
    for (int j = 0; j < 32; j += 8)
        t[ty + j][tx] = W[(size_t)(k0 + ty + j) * N + n0 + tx];
    __syncthreads();
#pragma unroll
    for (int j = 0; j < 32; j += 8)
        Wt[(size_t)(n0 + ty + j) * K + k0 + tx] = __float2half_rn(t[tx][ty + j]);
}

// ---------------------------------------------------------------------------
// fp16 mma GEMM:  C[M,N] = A[M,K] @ Bt[N,K]^T + bias[N]
// CTA 128x128, BK=64 (128B fp16 rows), 8 warps (2x4) of 64x32 tiles.
// 3-stage cp.async pipeline, ONE __syncthreads per k-tile.
// smem: 3 stages x (A 16KB + B 16KB) = 96KB.
// ---------------------------------------------------------------------------
#define GEMM_SMEM 98304

template<bool HALF_OUT>
__global__ __launch_bounds__(256)
void gemm_h(const __half* __restrict__ A, const __half* __restrict__ Bt,
            const float* __restrict__ bias, void* __restrict__ Cv,
            int M, int N, int K)
{
    extern __shared__ char smem[];
    const int tid  = threadIdx.x;
    const int lane = tid & 31;
    const int wid  = tid >> 5;
    const int warpM = wid >> 2;
    const int warpN = wid & 3;
    const int bm = blockIdx.y, bn = blockIdx.x;

    const __half* Ab = A  + (size_t)bm * 128 * K;
    const __half* Bb = Bt + (size_t)bn * 128 * K;

    float c[4][4][4];
#pragma unroll
    for (int i = 0; i < 4; i++)
#pragma unroll
        for (int j = 0; j < 4; j++)
#pragma unroll
            for (int e = 0; e < 4; e++) c[i][j][e] = 0.0f;

    const uint32_t sbase = (uint32_t)__cvta_generic_to_shared(smem);

    const int l7 = lane & 7;
    const uint32_t xorv = (uint32_t)l7 * 16u;
    const int rA = l7 + ((lane >> 3) & 1) * 8;
    const uint32_t kA = ((lane >> 4) & 1) * 16;
    uint32_t aRow[4];
#pragma unroll
    for (int i = 0; i < 4; i++)
        aRow[i] = (uint32_t)(warpM * 64 + i * 16 + rA) * 128u;
    const int rB = l7 + ((lane >> 4) & 1) * 8;
    const uint32_t kB = ((lane >> 3) & 1) * 16;
    uint32_t bRow[2];
#pragma unroll
    for (int j = 0; j < 2; j++)
        bRow[j] = (uint32_t)(warpN * 32 + j * 16 + rB) * 128u;

    const int NT = K / 64;   // = 16

#define LOAD_TILE(t, buf)                                                      \
    do {                                                                       \
        const int k0 = (t) * 64;                                               \
        char* sA = smem + (buf) * 32768;                                       \
        char* sB = sA + 16384;                                                 \
        _Pragma("unroll")                                                      \
        for (int i = 0; i < 4; i++) {                                          \
            const int idx = tid + i * 256;                                     \
            const int row = idx >> 3, ch = idx & 7;                            \
            const uint32_t off = SWZ((uint32_t)(row * 128 + ch * 16));         \
            cp_async16(sA + off, Ab + (size_t)row * K + k0 + ch * 8);          \
            cp_async16(sB + off, Bb + (size_t)row * K + k0 + ch * 8);          \
        }                                                                      \
    } while (0)

    LOAD_TILE(0, 0);
    CP_COMMIT();
    LOAD_TILE(1, 1);
    CP_COMMIT();

    int buf = 0;
    for (int t = 0; t < NT; t++) {
        if (t < NT - 1) { CP_WAIT(1); } else { CP_WAIT(0); }
        __syncthreads();   // all warps done with buf (t-1)%3 -> safe to refill
        if (t + 2 < NT) {
            int nb = buf + 2; if (nb >= 3) nb -= 3;
            LOAD_TILE(t + 2, nb);
            CP_COMMIT();
        }

        const uint32_t aBase = sbase + buf * 32768;
        const uint32_t bBase = aBase + 16384;

#pragma unroll
        for (int slab = 0; slab < 4; slab++) {
            const uint32_t so = (uint32_t)slab * 32u;
            uint32_t a[4][4], b[2][4];
#pragma unroll
            for (int i = 0; i < 4; i++)
                ldsm4(a[i], aBase + aRow[i] + ((so + kA) ^ xorv));
#pragma unroll
            for (int j = 0; j < 2; j++)
                ldsm4(b[j], bBase + bRow[j] + ((so + kB) ^ xorv));
#pragma unroll
            for (int mi = 0; mi < 4; mi++)
#pragma unroll
                for (int nj = 0; nj < 4; nj++)
                    mma16(c[mi][nj], a[mi],
                          b[nj >> 1][(nj & 1) * 2], b[nj >> 1][(nj & 1) * 2 + 1]);
        }
        if (++buf == 3) buf = 0;
    }
#undef LOAD_TILE

    // ---- epilogue: accumulators + bias ----
#pragma unroll
    for (int mi = 0; mi < 4; mi++) {
        const int row0 = bm * 128 + warpM * 64 + mi * 16 + (lane >> 2);
#pragma unroll
        for (int nj = 0; nj < 4; nj++) {
            const int col = bn * 128 + warpN * 32 + nj * 8 + (lane & 3) * 2;
            const float2 bv = *(const float2*)(bias + col);
            const float o00 = c[mi][nj][0] + bv.x, o01 = c[mi][nj][1] + bv.y;
            const float o10 = c[mi][nj][2] + bv.x, o11 = c[mi][nj][3] + bv.y;
            if (HALF_OUT) {
                __half* C = (__half*)Cv;
                __half2 h0 = __floats2half2_rn(o00, o01);
                __half2 h1 = __floats2half2_rn(o10, o11);
                *(__half2*)(C + (size_t)row0 * N + col) = h0;
                *(__half2*)(C + (size_t)(row0 + 8) * N + col) = h1;
            } else {
                float* C = (float*)Cv;
                *(float2*)(C + (size_t)row0 * N + col) = make_float2(o00, o01);
                *(float2*)(C + (size_t)(row0 + 8) * N + col) = make_float2(o10, o11);
            }
        }
    }
}

// ---------------------------------------------------------------------------
// fp16 tensor-core flash attention, 3-stage K/V pipeline, 1 sync per tile.
// Grid (NS/128, NH, NB), 256 threads (8 warps x 16 q-rows).
// smem (bytes): Q [128][64]h @0 (16KB), P [128][64]h @16384 (16KB),
//               3 stages x (K [64][64]h 8KB + V [64][64]h 8KB) @32768.
// Total 81920 bytes; 2 CTAs/SM.
// ---------------------------------------------------------------------------
#define ATTN_SMEM 81920
#define QOFF 0
#define POFF 16384
#define KVOFF 32768

__global__ __launch_bounds__(256, 2)
void attn_h(const __half* __restrict__ q, const __half* __restrict__ kv,
            __half* __restrict__ heads)
{
    extern __shared__ char smc[];
    const uint32_t sb = (uint32_t)__cvta_generic_to_shared(smc);

    const int b = blockIdx.z, h = blockIdx.y, qt = blockIdx.x;
    const int tid = threadIdx.x, lane = tid & 31, w = tid >> 5;
    const float scale = 0.125f;   // 1/sqrt(64)

    // ---- ldmatrix address precompute ----
    const int l7 = lane & 7;
    const uint32_t xorv = (uint32_t)l7 * 16u;
    const int rA = l7 + ((lane >> 3) & 1) * 8;
    const uint32_t kA = ((lane >> 4) & 1) * 16;
    const uint32_t aRowOff = (uint32_t)(w * 16 + rA) * 128u;

    const int rB = l7 + ((lane >> 4) & 1) * 8;
    const uint32_t kB = ((lane >> 3) & 1) * 16;
    uint32_t bRow[4];
#pragma unroll
    for (int j = 0; j < 4; j++)
        bRow[j] = (uint32_t)(j * 16 + rB) * 128u;

    // V trans-ldmatrix: lane -> source k row and d 16B-half
    const uint32_t vkOff = (uint32_t)(l7 + ((lane >> 3) & 1) * 8) * 128u;
    const uint32_t vdh = ((lane >> 4) & 1) * 16;

    // ---- load Q tile (fp16 direct copies; rides in cp.async group 0) ----
#pragma unroll
    for (int i = 0; i < 4; i++) {
        const int idx = tid + i * 256;
        const int row = idx >> 3, ch = idx & 7;
        cp_async16(smc + QOFF + SWZ((uint32_t)(row * 128 + ch * 16)),
                   q + (size_t)(b * NS + qt * 128 + row) * MD + h * HD + ch * 8);
    }

    // K/V tile loader (3-stage)
#define ATTN_LOAD(kt, buf)                                                     \
    do {                                                                       \
        _Pragma("unroll")                                                      \
        for (int i = 0; i < 2; i++) {                                          \
            const int idx = tid + i * 256;                                     \
            const int row = idx >> 3, ch = idx & 7;                            \
            const __half* src = kv + (size_t)(b * NS + (kt) * 64 + row) * (2 * MD) \
                              + h * HD + ch * 8;                               \
            const uint32_t off = SWZ((uint32_t)(row * 128 + ch * 16));         \
            cp_async16(smc + KVOFF + (buf) * 16384 + off, src);                \
            cp_async16(smc + KVOFF + (buf) * 16384 + 8192 + off, src + MD);    \
        }                                                                      \
    } while (0)

    ATTN_LOAD(0, 0);
    CP_COMMIT();
    ATTN_LOAD(1, 1);
    CP_COMMIT();

    float O[8][4];
#pragma unroll
    for (int nj = 0; nj < 8; nj++)
#pragma unroll
        for (int e = 0; e < 4; e++) O[nj][e] = 0.0f;
    float m_run[2] = { -INFINITY, -INFINITY };
    float l_run[2] = { 0.0f, 0.0f };

    const int NKT = NS / 64;   // 16
    int buf = 0;
    for (int kt = 0; kt < NKT; kt++) {
        if (kt < NKT - 1) { CP_WAIT(1); } else { CP_WAIT(0); }
        __syncthreads();   // all warps done reading buf (kt-1)%3
        if (kt + 2 < NKT) {
            int nb = buf + 2; if (nb >= 3) nb -= 3;
            ATTN_LOAD(kt + 2, nb);
            CP_COMMIT();
        }

        const uint32_t Kb = sb + KVOFF + buf * 16384;
        const uint32_t Vb = Kb + 8192;

        // ---- S = Q K^T  (warp: 16 q-rows x 64 keys) ----
        float sacc[8][4];
#pragma unroll
        for (int nj = 0; nj < 8; nj++)
#pragma unroll
            for (int e = 0; e < 4; e++) sacc[nj][e] = 0.0f;

#pragma unroll
        for (int s = 0; s < 4; s++) {
            const uint32_t so = (uint32_t)s * 32u;
            uint32_t a[4], kb[4][4];
            ldsm4(a, sb + QOFF + aRowOff + ((so + kA) ^ xorv));
#pragma unroll
            for (int j = 0; j < 4; j++)
                ldsm4(kb[j], Kb + bRow[j] + ((so + kB) ^ xorv));
#pragma unroll
            for (int j = 0; j < 4; j++) {
                mma16(sacc[2 * j],     a, kb[j][0], kb[j][1]);
                mma16(sacc[2 * j + 1], a, kb[j][2], kb[j][3]);
            }
        }

        // ---- scale + online softmax + P store (fp16) ----
#pragma unroll
        for (int nj = 0; nj < 8; nj++)
#pragma unroll
            for (int e = 0; e < 4; e++) sacc[nj][e] *= scale;

#pragma unroll
        for (int r = 0; r < 2; r++) {
            float mx = -INFINITY;
#pragma unroll
            for (int nj = 0; nj < 8; nj++)
                mx = fmaxf(mx, fmaxf(sacc[nj][2 * r], sacc[nj][2 * r + 1]));
            mx = fmaxf(mx, __shfl_xor_sync(0xffffffffu, mx, 1));
            mx = fmaxf(mx, __shfl_xor_sync(0xffffffffu, mx, 2));

            const float m_new = fmaxf(m_run[r], mx);
            const float al = __expf(m_run[r] - m_new);
            float sum = 0.0f;
#pragma unroll
            for (int nj = 0; nj < 8; nj++) {
                const float p0 = __expf(sacc[nj][2 * r] - m_new);
                const float p1 = __expf(sacc[nj][2 * r + 1] - m_new);
                sacc[nj][2 * r] = p0; sacc[nj][2 * r + 1] = p1;
                sum += p0 + p1;
            }
            sum += __shfl_xor_sync(0xffffffffu, sum, 1);
            sum += __shfl_xor_sync(0xffffffffu, sum, 2);

            l_run[r] = l_run[r] * al + sum;
            m_run[r] = m_new;
#pragma unroll
            for (int nj = 0; nj < 8; nj++) {
                O[nj][2 * r] *= al;
                O[nj][2 * r + 1] *= al;
            }
            const int prow = w * 16 + (lane >> 2) + r * 8;
#pragma unroll
            for (int nj = 0; nj < 8; nj++) {
                __half2 pv = __floats2half2_rn(sacc[nj][2 * r], sacc[nj][2 * r + 1]);
                *(uint32_t*)(smc + POFF +
                    SWZ((uint32_t)(prow * 128 + nj * 16 + (lane & 3) * 4))) =
                    *(uint32_t*)&pv;
            }
        }
        __syncwarp();   // P rows are warp-private; order stores before ldmatrix

        // ---- O += P V   (V via ldmatrix.trans: B[d][k] from V[k][d]) ----
#pragma unroll
        for (int s = 0; s < 4; s++) {
            const uint32_t so = (uint32_t)s * 32u;
            uint32_t a[4];
            ldsm4(a, sb + POFF + aRowOff + ((so + kA) ^ xorv));
#pragma unroll
            for (int jb = 0; jb < 4; jb++) {
                uint32_t bb[4];
                ldsm4t(bb, Vb + s * 2048 + vkOff + ((jb * 32 + vdh) ^ xorv));
                mma16(O[2 * jb],     a, bb[0], bb[1]);
                mma16(O[2 * jb + 1], a, bb[2], bb[3]);
            }
        }
        if (++buf == 3) buf = 0;
    }
#undef ATTN_LOAD

    // ---- normalize and write heads (fp16) ----
#pragma unroll
    for (int r = 0; r < 2; r++) {
        const float inv = 1.0f / l_run[r];
        const size_t row = (size_t)(b * NS + qt * 128 + w * 16 + (lane >> 2) + r * 8);
#pragma unroll
        for (int nj = 0; nj < 8; nj++) {
            const int col = h * HD + nj * 8 + (lane & 3) * 2;
            __half2 o = __floats2half2_rn(O[nj][2 * r] * inv, O[nj][2 * r + 1] * inv);
            *(__half2*)(heads + row * MD + col) = o;
        }
    }
}

// ---------------------------------------------------------------------------
extern "C" void kernel_launch(void* const* d_in, const int* in_sizes, int n_in,
                              void* d_out, int out_size)
{
    (void)in_sizes; (void)n_in; (void)out_size;
    const float* query = (const float*)d_in[0];
    const float* value = (const float*)d_in[1];
    const float* Wq    = (const float*)d_in[2];
    const float* bq    = (const float*)d_in[3];
    const float* Wkv   = (const float*)d_in[4];
    const float* bkv   = (const float*)d_in[5];
    const float* Wo    = (const float*)d_in[6];
    const float* bo    = (const float*)d_in[7];
    float* out = (float*)d_out;

    __half *xh, *q16, *kv16, *h16, *wt16;
    cudaGetSymbolAddress((void**)&xh,   g_xh);
    cudaGetSymbolAddress((void**)&q16,  g_q16);
    cudaGetSymbolAddress((void**)&kv16, g_kv16);
    cudaGetSymbolAddress((void**)&h16,  g_h16);
    cudaGetSymbolAddress((void**)&wt16, g_wt16);

    cudaFuncSetAttribute(attn_h,
                         cudaFuncAttributeMaxDynamicSharedMemorySize, ATTN_SMEM);
    cudaFuncSetAttribute(gemm_h<true>,
                         cudaFuncAttributeMaxDynamicSharedMemorySize, GEMM_SMEM);
    cudaFuncSetAttribute(gemm_h<false>,
                         cudaFuncAttributeMaxDynamicSharedMemorySize, GEMM_SMEM);

    const dim3 tblk(32, 8);
    const int n4 = MROWS * MD / 4;

    // ---- q = query @ Wq + bq ----
    f2h<<<2048, 256>>>(query, xh, n4);
    transpose_h<<<dim3(MD / 32, MD / 32), tblk>>>(Wq, wt16, MD, MD);
    gemm_h<true><<<dim3(MD / 128, MROWS / 128), 256, GEMM_SMEM>>>(
        xh, wt16, bq, q16, MROWS, MD, MD);

    // ---- kv = value @ Wkv + bkv ----
    f2h<<<2048, 256>>>(value, xh, n4);
    transpose_h<<<dim3(2 * MD / 32, MD / 32), tblk>>>(Wkv, wt16, MD, 2 * MD);
    gemm_h<true><<<dim3(2 * MD / 128, MROWS / 128), 256, GEMM_SMEM>>>(
        xh, wt16, bkv, kv16, MROWS, 2 * MD, MD);

    // ---- fused fp16 tensor-core attention ----
    attn_h<<<dim3(NS / 128, NH, NB), 256, ATTN_SMEM>>>(q16, kv16, h16);

    // ---- out = heads @ Wo + bo ----
    transpose_h<<<dim3(MD / 32, MD / 32), tblk>>>(Wo, wt16, MD, MD);
    gemm_h<false><<<dim3(MD / 128, MROWS / 128), 256, GEMM_SMEM>>>(
        h16, wt16, bo, out, MROWS, MD, MD);
}